// round 9
// baseline (speedup 1.0000x reference)
#include <cuda_runtime.h>
#include <cuda_bf16.h>
#include <cstdint>
#include <cstdio>

// Problem constants
#define NN    10000
#define TT    60
#define FF    16
#define HL    256
#define G4H   1024     // 4*HL
#define GH    8
#define GC    64
#define GD    512
#define FH    512
#define EMAX  320000
#define ETOTMAX (EMAX + NN)

// ---------------- device scratch (no allocations allowed) ----------------
__device__ float g_h0[NN * HL];
__device__ float g_c0[NN * HL];
__device__ float g_h1[NN * HL];
__device__ float g_c1[NN * HL];
__device__ float g_gates[NN * G4H];
__device__ float g_xl[NN * GD];
__device__ float g_xr[NN * GD];
__device__ float g_gout[NN * GD];
__device__ float g_gin[NN * GD];
__device__ float g_den[NN * GH];
__device__ float g_expl[ETOTMAX * GH];
__device__ float g_fc1[NN * FH];
__device__ float g_partial[256];
__device__ float g_mean_buf[1];

// ---------------- GEMM: C = A1@op(B1) + A2@op(B2) + bias1 + bias2 --------
// transB=1: B is [M x K] row-major (A @ B^T)   (LSTM weights)
// transB=0: B is [K x M] row-major (A @ B)     (GAT / MLP weights)
// act: 0 none, 1 relu
#define BM 128
#define BN 128
#define BK 8

__global__ __launch_bounds__(256) void gemm_dual(
    const float* __restrict__ A1, int lda1, int K1, const float* __restrict__ B1,
    const float* __restrict__ A2, int lda2, int K2, const float* __restrict__ B2,
    const float* __restrict__ bias1, const float* __restrict__ bias2,
    float* __restrict__ C, int Nr, int M, int transB, int act)
{
    __shared__ float As[BK][BM];
    __shared__ float Bs[BK][BN];

    const int tid = threadIdx.x;
    const int tx = tid & 15;        // 0..15 -> col group of 8
    const int ty = tid >> 4;        // 0..15 -> row group of 8
    const int rowBase = blockIdx.y * BM;
    const int colBase = blockIdx.x * BN;

    float acc[8][8];
#pragma unroll
    for (int i = 0; i < 8; i++)
#pragma unroll
        for (int j = 0; j < 8; j++) acc[i][j] = 0.f;

    for (int phase = 0; phase < 2; phase++) {
        const float* A = phase ? A2 : A1;
        const float* B = phase ? B2 : B1;
        const int K   = phase ? K2 : K1;
        const int lda = phase ? lda2 : lda1;
        for (int k0 = 0; k0 < K; k0 += BK) {
            // load A tile: As[k][m]
            {
                int r  = tid >> 1;
                int kq = (tid & 1) * 4;
                int gr = rowBase + r;
                float4 v = make_float4(0.f, 0.f, 0.f, 0.f);
                if (gr < Nr)
                    v = *(const float4*)(A + (size_t)gr * lda + k0 + kq);
                As[kq + 0][r] = v.x; As[kq + 1][r] = v.y;
                As[kq + 2][r] = v.z; As[kq + 3][r] = v.w;
            }
            // load B tile: Bs[k][n]
            if (transB) {
                int r  = tid >> 1;                 // output col within tile
                int kq = (tid & 1) * 4;
                float4 v = *(const float4*)(B + (size_t)(colBase + r) * K + k0 + kq);
                Bs[kq + 0][r] = v.x; Bs[kq + 1][r] = v.y;
                Bs[kq + 2][r] = v.z; Bs[kq + 3][r] = v.w;
            } else {
                int kk = tid >> 5;                 // 0..7
                int n4 = (tid & 31) * 4;
                float4 v = *(const float4*)(B + (size_t)(k0 + kk) * M + colBase + n4);
                Bs[kk][n4 + 0] = v.x; Bs[kk][n4 + 1] = v.y;
                Bs[kk][n4 + 2] = v.z; Bs[kk][n4 + 3] = v.w;
            }
            __syncthreads();
#pragma unroll
            for (int k = 0; k < BK; k++) {
                float4 a0 = *(const float4*)&As[k][ty * 8];
                float4 a1 = *(const float4*)&As[k][ty * 8 + 4];
                float4 b0 = *(const float4*)&Bs[k][tx * 8];
                float4 b1 = *(const float4*)&Bs[k][tx * 8 + 4];
                float ra[8] = {a0.x, a0.y, a0.z, a0.w, a1.x, a1.y, a1.z, a1.w};
                float rb[8] = {b0.x, b0.y, b0.z, b0.w, b1.x, b1.y, b1.z, b1.w};
#pragma unroll
                for (int i = 0; i < 8; i++)
#pragma unroll
                    for (int j = 0; j < 8; j++)
                        acc[i][j] = fmaf(ra[i], rb[j], acc[i][j]);
            }
            __syncthreads();
        }
    }

#pragma unroll
    for (int i = 0; i < 8; i++) {
        int gr = rowBase + ty * 8 + i;
        if (gr >= Nr) continue;
#pragma unroll
        for (int j = 0; j < 8; j++) {
            int gc = colBase + tx * 8 + j;
            float v = acc[i][j];
            if (bias1) v += bias1[gc];
            if (bias2) v += bias2[gc];
            if (act == 1) v = fmaxf(v, 0.f);
            C[(size_t)gr * M + gc] = v;
        }
    }
}

// ---------------- LSTM cell pointwise -------------------------------------
__global__ void lstm_cell(const float* __restrict__ gates,
                          float* __restrict__ h, float* __restrict__ c, int total)
{
    int idx = blockIdx.x * blockDim.x + threadIdx.x;
    if (idx >= total) return;
    int row = idx >> 8;          // /256
    int j   = idx & 255;
    const float* g = gates + (size_t)row * G4H;
    float gi = g[j], gf = g[j + HL], gg = g[j + 2 * HL], go = g[j + 3 * HL];
    float si = 1.f / (1.f + __expf(-gi));
    float sf = 1.f / (1.f + __expf(-gf));
    float so = 1.f / (1.f + __expf(-go));
    float cn = sf * c[idx] + si * tanhf(gg);
    c[idx] = cn;
    h[idx] = so * tanhf(cn);
}

// ---------------- edge_attr mean (deterministic 2-stage) -------------------
__global__ void reduce_mean1(const float* __restrict__ ea, int E)
{
    __shared__ float s[256];
    int tid = threadIdx.x;
    float acc = 0.f;
    for (int i = blockIdx.x * 256 + tid; i < E; i += 256 * 256) acc += ea[i];
    s[tid] = acc;
    __syncthreads();
    for (int off = 128; off > 0; off >>= 1) {
        if (tid < off) s[tid] += s[tid + off];
        __syncthreads();
    }
    if (tid == 0) g_partial[blockIdx.x] = s[0];
}

__global__ void reduce_mean2(int E)
{
    __shared__ float s[256];
    int tid = threadIdx.x;
    s[tid] = g_partial[tid];
    __syncthreads();
    for (int off = 128; off > 0; off >>= 1) {
        if (tid < off) s[tid] += s[tid + off];
        __syncthreads();
    }
    if (tid == 0) g_mean_buf[0] = s[0] / (float)E;
}

// ---------------- GAT edge pass 1: logits -> exp, accumulate denominator ---
// Softmax computed without max-subtraction: for this data distribution the
// logits are bounded (|logit| < ~30), exp() is safe in fp32, and the result
// is mathematically identical.
__global__ void gat_edge_logits(
    const int* __restrict__ src, const int* __restrict__ dst,
    const float* __restrict__ ea,
    const float* __restrict__ we, const float* __restrict__ att,
    const float* __restrict__ xl, const float* __restrict__ xr,
    float* __restrict__ expl, float* __restrict__ den,
    int E, int Etot)
{
    int idx = blockIdx.x * blockDim.x + threadIdx.x;
    if (idx >= Etot * GH) return;
    int e = idx >> 3;
    int h = idx & 7;
    int s, d; float a;
    if (e < E) { s = src[e]; d = dst[e]; a = ea[e]; }
    else       { s = d = e - E;          a = g_mean_buf[0]; }

    const float4* pl = (const float4*)(xl + (size_t)s * GD + h * GC);
    const float4* pr = (const float4*)(xr + (size_t)d * GD + h * GC);
    const float4* pw = (const float4*)(we + h * GC);
    const float4* pa = (const float4*)(att + h * GC);

    float acc = 0.f;
#pragma unroll
    for (int c4 = 0; c4 < GC / 4; c4++) {
        float4 vl = pl[c4], vr = pr[c4], vw = pw[c4], va = pa[c4];
        float m;
        m = vl.x + vr.x + a * vw.x; m = m > 0.f ? m : 0.2f * m; acc += m * va.x;
        m = vl.y + vr.y + a * vw.y; m = m > 0.f ? m : 0.2f * m; acc += m * va.y;
        m = vl.z + vr.z + a * vw.z; m = m > 0.f ? m : 0.2f * m; acc += m * va.z;
        m = vl.w + vr.w + a * vw.w; m = m > 0.f ? m : 0.2f * m; acc += m * va.w;
    }
    float ex = __expf(acc);
    expl[idx] = ex;
    atomicAdd(&den[d * GH + h], ex);
}

// ---------------- GAT edge pass 2: weighted aggregation --------------------
__global__ void gat_edge_aggr(
    const int* __restrict__ src, const int* __restrict__ dst,
    const float* __restrict__ xl,
    const float* __restrict__ expl, const float* __restrict__ den,
    float* __restrict__ gout,
    int E, int Etot)
{
    int idx = blockIdx.x * blockDim.x + threadIdx.x;
    if (idx >= Etot * GH) return;
    int e = idx >> 3;
    int h = idx & 7;
    int s, d;
    if (e < E) { s = src[e]; d = dst[e]; }
    else       { s = d = e - E; }

    float alpha = expl[idx] / den[d * GH + h];
    const float4* pl = (const float4*)(xl + (size_t)s * GD + h * GC);
    float* po = gout + (size_t)d * GD + h * GC;
#pragma unroll
    for (int c4 = 0; c4 < GC / 4; c4++) {
        float4 v = pl[c4];
        atomicAdd(&po[c4 * 4 + 0], v.x * alpha);
        atomicAdd(&po[c4 * 4 + 1], v.y * alpha);
        atomicAdd(&po[c4 * 4 + 2], v.z * alpha);
        atomicAdd(&po[c4 * 4 + 3], v.w * alpha);
    }
}

// ---------------- GAT finalize: +bias, ELU ---------------------------------
__global__ void gat_finalize(const float* __restrict__ gout,
                             const float* __restrict__ bias,
                             float* __restrict__ out, int total)
{
    int idx = blockIdx.x * blockDim.x + threadIdx.x;
    if (idx >= total) return;
    float v = gout[idx] + bias[idx & (GD - 1)];
    out[idx] = v > 0.f ? v : expm1f(v);
}

// ---------------- fc2 GEMV -------------------------------------------------
__global__ void gemv_fc2(const float* __restrict__ hbuf,
                         const float* __restrict__ w, const float* __restrict__ b,
                         float* __restrict__ out, int n)
{
    int gw = (blockIdx.x * blockDim.x + threadIdx.x) >> 5;
    int lane = threadIdx.x & 31;
    if (gw >= n) return;
    const float* row = hbuf + (size_t)gw * FH;
    float acc = 0.f;
#pragma unroll
    for (int k = lane; k < FH; k += 32) acc += row[k] * w[k];
#pragma unroll
    for (int off = 16; off > 0; off >>= 1) acc += __shfl_xor_sync(0xffffffffu, acc, off);
    if (lane == 0) out[gw] = acc + b[0];
}

// ---------------- host orchestration ---------------------------------------
static inline void run_gemm(const float* A1, int lda1, int K1, const float* B1,
                            const float* A2, int lda2, int K2, const float* B2,
                            const float* bias1, const float* bias2,
                            float* C, int Nr, int M, int transB, int act)
{
    dim3 grid((M + BN - 1) / BN, (Nr + BM - 1) / BM);
    gemm_dual<<<grid, 256>>>(A1, lda1, K1, B1, A2, lda2, K2, B2,
                             bias1, bias2, C, Nr, M, transB, act);
}

extern "C" void kernel_launch(void* const* d_in, const int* in_sizes, int n_in,
                              void* d_out, int out_size)
{
    const float* x_seq  = (const float*)d_in[0];
    const int*   eidx   = (const int*)  d_in[1];
    const float* eattr  = (const float*)d_in[2];
    const float* w_ih0  = (const float*)d_in[3];
    const float* w_hh0  = (const float*)d_in[4];
    const float* b_ih0  = (const float*)d_in[5];
    const float* b_hh0  = (const float*)d_in[6];
    const float* w_ih1  = (const float*)d_in[7];
    const float* w_hh1  = (const float*)d_in[8];
    const float* b_ih1  = (const float*)d_in[9];
    const float* b_hh1  = (const float*)d_in[10];
    const float* g0_wl  = (const float*)d_in[11];
    const float* g0_bl  = (const float*)d_in[12];
    const float* g0_wr  = (const float*)d_in[13];
    const float* g0_br  = (const float*)d_in[14];
    const float* g0_we  = (const float*)d_in[15];
    const float* g0_att = (const float*)d_in[16];
    const float* g0_bias= (const float*)d_in[17];
    const float* g1_wl  = (const float*)d_in[18];
    const float* g1_bl  = (const float*)d_in[19];
    const float* g1_wr  = (const float*)d_in[20];
    const float* g1_br  = (const float*)d_in[21];
    const float* g1_we  = (const float*)d_in[22];
    const float* g1_att = (const float*)d_in[23];
    const float* g1_bias= (const float*)d_in[24];
    const float* fc1_w  = (const float*)d_in[25];
    const float* fc1_b  = (const float*)d_in[26];
    const float* fc2_w  = (const float*)d_in[27];
    const float* fc2_b  = (const float*)d_in[28];

    const int n = in_sizes[0] / (TT * FF);
    const int E = in_sizes[2];
    const int Etot = E + n;
    const int* src = eidx;
    const int* dst = eidx + E;

    float *h0, *c0, *h1, *c1, *gates, *xl, *xr, *gout, *gin, *den, *expl, *fc1buf;
    cudaGetSymbolAddress((void**)&h0, g_h0);
    cudaGetSymbolAddress((void**)&c0, g_c0);
    cudaGetSymbolAddress((void**)&h1, g_h1);
    cudaGetSymbolAddress((void**)&c1, g_c1);
    cudaGetSymbolAddress((void**)&gates, g_gates);
    cudaGetSymbolAddress((void**)&xl, g_xl);
    cudaGetSymbolAddress((void**)&xr, g_xr);
    cudaGetSymbolAddress((void**)&gout, g_gout);
    cudaGetSymbolAddress((void**)&gin, g_gin);
    cudaGetSymbolAddress((void**)&den, g_den);
    cudaGetSymbolAddress((void**)&expl, g_expl);
    cudaGetSymbolAddress((void**)&fc1buf, g_fc1);

    // init states
    cudaMemsetAsync(h0, 0, (size_t)n * HL * sizeof(float));
    cudaMemsetAsync(c0, 0, (size_t)n * HL * sizeof(float));
    cudaMemsetAsync(h1, 0, (size_t)n * HL * sizeof(float));
    cudaMemsetAsync(c1, 0, (size_t)n * HL * sizeof(float));

    // edge_attr mean (for self-loop fill)
    reduce_mean1<<<256, 256>>>(eattr, E);
    reduce_mean2<<<1, 256>>>(E);

    // ------------- LSTM: 2 layers interleaved over 60 steps -------------
    const int cellThreads = n * HL;
    for (int t = 0; t < TT; t++) {
        // layer 0: gates = x_t @ w_ih0^T + h0 @ w_hh0^T + b
        run_gemm(x_seq + (size_t)t * FF, TT * FF, FF, w_ih0,
                 h0, HL, HL, w_hh0,
                 b_ih0, b_hh0, gates, n, G4H, /*transB=*/1, 0);
        lstm_cell<<<(cellThreads + 255) / 256, 256>>>(gates, h0, c0, cellThreads);
        // layer 1: gates = h0 @ w_ih1^T + h1 @ w_hh1^T + b
        run_gemm(h0, HL, HL, w_ih1,
                 h1, HL, HL, w_hh1,
                 b_ih1, b_hh1, gates, n, G4H, 1, 0);
        lstm_cell<<<(cellThreads + 255) / 256, 256>>>(gates, h1, c1, cellThreads);
    }
    // node features = h1 (layer-1 hidden at last step)

    const int edgeThreads = Etot * GH;
    const int edgeBlocks  = (edgeThreads + 255) / 256;
    const int ndTot = n * GD;

    // ------------- GAT layer 0 (input: h1, K=256) -------------
    run_gemm(h1, HL, HL, g0_wl, nullptr, 0, 0, nullptr, g0_bl, nullptr,
             xl, n, GD, /*transB=*/0, 0);
    run_gemm(h1, HL, HL, g0_wr, nullptr, 0, 0, nullptr, g0_br, nullptr,
             xr, n, GD, 0, 0);
    cudaMemsetAsync(den, 0, (size_t)n * GH * sizeof(float));
    cudaMemsetAsync(gout, 0, (size_t)ndTot * sizeof(float));
    gat_edge_logits<<<edgeBlocks, 256>>>(src, dst, eattr, g0_we, g0_att,
                                         xl, xr, expl, den, E, Etot);
    gat_edge_aggr<<<edgeBlocks, 256>>>(src, dst, xl, expl, den, gout, E, Etot);
    gat_finalize<<<(ndTot + 255) / 256, 256>>>(gout, g0_bias, gin, ndTot);

    // ------------- GAT layer 1 (input: gin, K=512) -------------
    run_gemm(gin, GD, GD, g1_wl, nullptr, 0, 0, nullptr, g1_bl, nullptr,
             xl, n, GD, 0, 0);
    run_gemm(gin, GD, GD, g1_wr, nullptr, 0, 0, nullptr, g1_br, nullptr,
             xr, n, GD, 0, 0);
    cudaMemsetAsync(den, 0, (size_t)n * GH * sizeof(float));
    cudaMemsetAsync(gout, 0, (size_t)ndTot * sizeof(float));
    gat_edge_logits<<<edgeBlocks, 256>>>(src, dst, eattr, g1_we, g1_att,
                                         xl, xr, expl, den, E, Etot);
    gat_edge_aggr<<<edgeBlocks, 256>>>(src, dst, xl, expl, den, gout, E, Etot);
    gat_finalize<<<(ndTot + 255) / 256, 256>>>(gout, g1_bias, gin, ndTot);

    // ------------- fusion MLP -------------
    // fc1: relu( [node | g] @ fc1_w + b ) via dual-A GEMM (concat split)
    run_gemm(h1, HL, HL, fc1_w,
             gin, GD, GD, fc1_w + (size_t)HL * FH,
             fc1_b, nullptr, fc1buf, n, FH, /*transB=*/0, /*act=*/1);
    // fc2: [n,512] @ [512,1]
    gemv_fc2<<<(n * 32 + 255) / 256, 256>>>(fc1buf, fc2_w, fc2_b,
                                            (float*)d_out, n);
}

// round 10
// speedup vs baseline: 1.0007x; 1.0007x over previous
#include <cuda_runtime.h>
#include <cuda_bf16.h>
#include <cstdint>
#include <cstdio>

// Problem constants
#define NN    10000
#define TT    60
#define FF    16
#define HL    256
#define G4H   1024     // 4*HL
#define GH    8
#define GC    64
#define GD    512
#define FH    512
#define EMAX  320000
#define ETOTMAX (EMAX + NN)

// ---------------- device scratch (no allocations allowed) ----------------
__device__ float g_h0[NN * HL];
__device__ float g_c0[NN * HL];
__device__ float g_h1[NN * HL];
__device__ float g_c1[NN * HL];
__device__ float g_gates[NN * G4H];
__device__ float g_xl[NN * GD];
__device__ float g_xr[NN * GD];
__device__ float g_gout[NN * GD];
__device__ float g_gin[NN * GD];
__device__ float g_den[NN * GH];
__device__ float g_expl[ETOTMAX * GH];
__device__ float g_fc1[NN * FH];
__device__ float g_partial[256];
__device__ float g_mean_buf[1];

// ---------------- GEMM: C = A1@op(B1) + A2@op(B2) + bias1 + bias2 --------
// transB=1: B is [M x K] row-major (A @ B^T)   (LSTM weights)
// transB=0: B is [K x M] row-major (A @ B)     (GAT / MLP weights)
// act: 0 none, 1 relu
#define BM 128
#define BN 128
#define BK 8

__global__ __launch_bounds__(256) void gemm_dual(
    const float* __restrict__ A1, int lda1, int K1, const float* __restrict__ B1,
    const float* __restrict__ A2, int lda2, int K2, const float* __restrict__ B2,
    const float* __restrict__ bias1, const float* __restrict__ bias2,
    float* __restrict__ C, int Nr, int M, int transB, int act)
{
    __shared__ float As[BK][BM];
    __shared__ float Bs[BK][BN];

    const int tid = threadIdx.x;
    const int tx = tid & 15;        // 0..15 -> col group of 8
    const int ty = tid >> 4;        // 0..15 -> row group of 8
    const int rowBase = blockIdx.y * BM;
    const int colBase = blockIdx.x * BN;

    float acc[8][8];
#pragma unroll
    for (int i = 0; i < 8; i++)
#pragma unroll
        for (int j = 0; j < 8; j++) acc[i][j] = 0.f;

    for (int phase = 0; phase < 2; phase++) {
        const float* A = phase ? A2 : A1;
        const float* B = phase ? B2 : B1;
        const int K   = phase ? K2 : K1;
        const int lda = phase ? lda2 : lda1;
        for (int k0 = 0; k0 < K; k0 += BK) {
            // load A tile: As[k][m]
            {
                int r  = tid >> 1;
                int kq = (tid & 1) * 4;
                int gr = rowBase + r;
                float4 v = make_float4(0.f, 0.f, 0.f, 0.f);
                if (gr < Nr)
                    v = *(const float4*)(A + (size_t)gr * lda + k0 + kq);
                As[kq + 0][r] = v.x; As[kq + 1][r] = v.y;
                As[kq + 2][r] = v.z; As[kq + 3][r] = v.w;
            }
            // load B tile: Bs[k][n]
            if (transB) {
                int r  = tid >> 1;                 // output col within tile
                int kq = (tid & 1) * 4;
                float4 v = *(const float4*)(B + (size_t)(colBase + r) * K + k0 + kq);
                Bs[kq + 0][r] = v.x; Bs[kq + 1][r] = v.y;
                Bs[kq + 2][r] = v.z; Bs[kq + 3][r] = v.w;
            } else {
                int kk = tid >> 5;                 // 0..7
                int n4 = (tid & 31) * 4;
                float4 v = *(const float4*)(B + (size_t)(k0 + kk) * M + colBase + n4);
                Bs[kk][n4 + 0] = v.x; Bs[kk][n4 + 1] = v.y;
                Bs[kk][n4 + 2] = v.z; Bs[kk][n4 + 3] = v.w;
            }
            __syncthreads();
#pragma unroll
            for (int k = 0; k < BK; k++) {
                float4 a0 = *(const float4*)&As[k][ty * 8];
                float4 a1 = *(const float4*)&As[k][ty * 8 + 4];
                float4 b0 = *(const float4*)&Bs[k][tx * 8];
                float4 b1 = *(const float4*)&Bs[k][tx * 8 + 4];
                float ra[8] = {a0.x, a0.y, a0.z, a0.w, a1.x, a1.y, a1.z, a1.w};
                float rb[8] = {b0.x, b0.y, b0.z, b0.w, b1.x, b1.y, b1.z, b1.w};
#pragma unroll
                for (int i = 0; i < 8; i++)
#pragma unroll
                    for (int j = 0; j < 8; j++)
                        acc[i][j] = fmaf(ra[i], rb[j], acc[i][j]);
            }
            __syncthreads();
        }
    }

#pragma unroll
    for (int i = 0; i < 8; i++) {
        int gr = rowBase + ty * 8 + i;
        if (gr >= Nr) continue;
#pragma unroll
        for (int j = 0; j < 8; j++) {
            int gc = colBase + tx * 8 + j;
            float v = acc[i][j];
            if (bias1) v += bias1[gc];
            if (bias2) v += bias2[gc];
            if (act == 1) v = fmaxf(v, 0.f);
            C[(size_t)gr * M + gc] = v;
        }
    }
}

// ---------------- LSTM cell pointwise -------------------------------------
__global__ void lstm_cell(const float* __restrict__ gates,
                          float* __restrict__ h, float* __restrict__ c, int total)
{
    int idx = blockIdx.x * blockDim.x + threadIdx.x;
    if (idx >= total) return;
    int row = idx >> 8;          // /256
    int j   = idx & 255;
    const float* g = gates + (size_t)row * G4H;
    float gi = g[j], gf = g[j + HL], gg = g[j + 2 * HL], go = g[j + 3 * HL];
    float si = 1.f / (1.f + __expf(-gi));
    float sf = 1.f / (1.f + __expf(-gf));
    float so = 1.f / (1.f + __expf(-go));
    float cn = sf * c[idx] + si * tanhf(gg);
    c[idx] = cn;
    h[idx] = so * tanhf(cn);
}

// ---------------- edge_attr mean (deterministic 2-stage) -------------------
__global__ void reduce_mean1(const float* __restrict__ ea, int E)
{
    __shared__ float s[256];
    int tid = threadIdx.x;
    float acc = 0.f;
    for (int i = blockIdx.x * 256 + tid; i < E; i += 256 * 256) acc += ea[i];
    s[tid] = acc;
    __syncthreads();
    for (int off = 128; off > 0; off >>= 1) {
        if (tid < off) s[tid] += s[tid + off];
        __syncthreads();
    }
    if (tid == 0) g_partial[blockIdx.x] = s[0];
}

__global__ void reduce_mean2(int E)
{
    __shared__ float s[256];
    int tid = threadIdx.x;
    s[tid] = g_partial[tid];
    __syncthreads();
    for (int off = 128; off > 0; off >>= 1) {
        if (tid < off) s[tid] += s[tid + off];
        __syncthreads();
    }
    if (tid == 0) g_mean_buf[0] = s[0] / (float)E;
}

// ---------------- GAT edge pass 1: logits -> exp, accumulate denominator ---
// Softmax computed without max-subtraction: for this data distribution the
// logits are bounded (|logit| < ~30), exp() is safe in fp32, and the result
// is mathematically identical.
__global__ void gat_edge_logits(
    const int* __restrict__ src, const int* __restrict__ dst,
    const float* __restrict__ ea,
    const float* __restrict__ we, const float* __restrict__ att,
    const float* __restrict__ xl, const float* __restrict__ xr,
    float* __restrict__ expl, float* __restrict__ den,
    int E, int Etot)
{
    int idx = blockIdx.x * blockDim.x + threadIdx.x;
    if (idx >= Etot * GH) return;
    int e = idx >> 3;
    int h = idx & 7;
    int s, d; float a;
    if (e < E) { s = src[e]; d = dst[e]; a = ea[e]; }
    else       { s = d = e - E;          a = g_mean_buf[0]; }

    const float4* pl = (const float4*)(xl + (size_t)s * GD + h * GC);
    const float4* pr = (const float4*)(xr + (size_t)d * GD + h * GC);
    const float4* pw = (const float4*)(we + h * GC);
    const float4* pa = (const float4*)(att + h * GC);

    float acc = 0.f;
#pragma unroll
    for (int c4 = 0; c4 < GC / 4; c4++) {
        float4 vl = pl[c4], vr = pr[c4], vw = pw[c4], va = pa[c4];
        float m;
        m = vl.x + vr.x + a * vw.x; m = m > 0.f ? m : 0.2f * m; acc += m * va.x;
        m = vl.y + vr.y + a * vw.y; m = m > 0.f ? m : 0.2f * m; acc += m * va.y;
        m = vl.z + vr.z + a * vw.z; m = m > 0.f ? m : 0.2f * m; acc += m * va.z;
        m = vl.w + vr.w + a * vw.w; m = m > 0.f ? m : 0.2f * m; acc += m * va.w;
    }
    float ex = __expf(acc);
    expl[idx] = ex;
    atomicAdd(&den[d * GH + h], ex);
}

// ---------------- GAT edge pass 2: weighted aggregation --------------------
__global__ void gat_edge_aggr(
    const int* __restrict__ src, const int* __restrict__ dst,
    const float* __restrict__ xl,
    const float* __restrict__ expl, const float* __restrict__ den,
    float* __restrict__ gout,
    int E, int Etot)
{
    int idx = blockIdx.x * blockDim.x + threadIdx.x;
    if (idx >= Etot * GH) return;
    int e = idx >> 3;
    int h = idx & 7;
    int s, d;
    if (e < E) { s = src[e]; d = dst[e]; }
    else       { s = d = e - E; }

    float alpha = expl[idx] / den[d * GH + h];
    const float4* pl = (const float4*)(xl + (size_t)s * GD + h * GC);
    float* po = gout + (size_t)d * GD + h * GC;
#pragma unroll
    for (int c4 = 0; c4 < GC / 4; c4++) {
        float4 v = pl[c4];
        atomicAdd(&po[c4 * 4 + 0], v.x * alpha);
        atomicAdd(&po[c4 * 4 + 1], v.y * alpha);
        atomicAdd(&po[c4 * 4 + 2], v.z * alpha);
        atomicAdd(&po[c4 * 4 + 3], v.w * alpha);
    }
}

// ---------------- GAT finalize: +bias, ELU ---------------------------------
__global__ void gat_finalize(const float* __restrict__ gout,
                             const float* __restrict__ bias,
                             float* __restrict__ out, int total)
{
    int idx = blockIdx.x * blockDim.x + threadIdx.x;
    if (idx >= total) return;
    float v = gout[idx] + bias[idx & (GD - 1)];
    out[idx] = v > 0.f ? v : expm1f(v);
}

// ---------------- fc2 GEMV -------------------------------------------------
__global__ void gemv_fc2(const float* __restrict__ hbuf,
                         const float* __restrict__ w, const float* __restrict__ b,
                         float* __restrict__ out, int n)
{
    int gw = (blockIdx.x * blockDim.x + threadIdx.x) >> 5;
    int lane = threadIdx.x & 31;
    if (gw >= n) return;
    const float* row = hbuf + (size_t)gw * FH;
    float acc = 0.f;
#pragma unroll
    for (int k = lane; k < FH; k += 32) acc += row[k] * w[k];
#pragma unroll
    for (int off = 16; off > 0; off >>= 1) acc += __shfl_xor_sync(0xffffffffu, acc, off);
    if (lane == 0) out[gw] = acc + b[0];
}

// ---------------- host orchestration ---------------------------------------
static inline void run_gemm(const float* A1, int lda1, int K1, const float* B1,
                            const float* A2, int lda2, int K2, const float* B2,
                            const float* bias1, const float* bias2,
                            float* C, int Nr, int M, int transB, int act)
{
    dim3 grid((M + BN - 1) / BN, (Nr + BM - 1) / BM);
    gemm_dual<<<grid, 256>>>(A1, lda1, K1, B1, A2, lda2, K2, B2,
                             bias1, bias2, C, Nr, M, transB, act);
}

extern "C" void kernel_launch(void* const* d_in, const int* in_sizes, int n_in,
                              void* d_out, int out_size)
{
    const float* x_seq  = (const float*)d_in[0];
    const int*   eidx   = (const int*)  d_in[1];
    const float* eattr  = (const float*)d_in[2];
    const float* w_ih0  = (const float*)d_in[3];
    const float* w_hh0  = (const float*)d_in[4];
    const float* b_ih0  = (const float*)d_in[5];
    const float* b_hh0  = (const float*)d_in[6];
    const float* w_ih1  = (const float*)d_in[7];
    const float* w_hh1  = (const float*)d_in[8];
    const float* b_ih1  = (const float*)d_in[9];
    const float* b_hh1  = (const float*)d_in[10];
    const float* g0_wl  = (const float*)d_in[11];
    const float* g0_bl  = (const float*)d_in[12];
    const float* g0_wr  = (const float*)d_in[13];
    const float* g0_br  = (const float*)d_in[14];
    const float* g0_we  = (const float*)d_in[15];
    const float* g0_att = (const float*)d_in[16];
    const float* g0_bias= (const float*)d_in[17];
    const float* g1_wl  = (const float*)d_in[18];
    const float* g1_bl  = (const float*)d_in[19];
    const float* g1_wr  = (const float*)d_in[20];
    const float* g1_br  = (const float*)d_in[21];
    const float* g1_we  = (const float*)d_in[22];
    const float* g1_att = (const float*)d_in[23];
    const float* g1_bias= (const float*)d_in[24];
    const float* fc1_w  = (const float*)d_in[25];
    const float* fc1_b  = (const float*)d_in[26];
    const float* fc2_w  = (const float*)d_in[27];
    const float* fc2_b  = (const float*)d_in[28];

    const int n = in_sizes[0] / (TT * FF);
    const int E = in_sizes[2];
    const int Etot = E + n;
    const int* src = eidx;
    const int* dst = eidx + E;

    float *h0, *c0, *h1, *c1, *gates, *xl, *xr, *gout, *gin, *den, *expl, *fc1buf;
    cudaGetSymbolAddress((void**)&h0, g_h0);
    cudaGetSymbolAddress((void**)&c0, g_c0);
    cudaGetSymbolAddress((void**)&h1, g_h1);
    cudaGetSymbolAddress((void**)&c1, g_c1);
    cudaGetSymbolAddress((void**)&gates, g_gates);
    cudaGetSymbolAddress((void**)&xl, g_xl);
    cudaGetSymbolAddress((void**)&xr, g_xr);
    cudaGetSymbolAddress((void**)&gout, g_gout);
    cudaGetSymbolAddress((void**)&gin, g_gin);
    cudaGetSymbolAddress((void**)&den, g_den);
    cudaGetSymbolAddress((void**)&expl, g_expl);
    cudaGetSymbolAddress((void**)&fc1buf, g_fc1);

    // init states
    cudaMemsetAsync(h0, 0, (size_t)n * HL * sizeof(float));
    cudaMemsetAsync(c0, 0, (size_t)n * HL * sizeof(float));
    cudaMemsetAsync(h1, 0, (size_t)n * HL * sizeof(float));
    cudaMemsetAsync(c1, 0, (size_t)n * HL * sizeof(float));

    // edge_attr mean (for self-loop fill)
    reduce_mean1<<<256, 256>>>(eattr, E);
    reduce_mean2<<<1, 256>>>(E);

    // ------------- LSTM: 2 layers interleaved over 60 steps -------------
    const int cellThreads = n * HL;
    for (int t = 0; t < TT; t++) {
        // layer 0: gates = x_t @ w_ih0^T + h0 @ w_hh0^T + b
        run_gemm(x_seq + (size_t)t * FF, TT * FF, FF, w_ih0,
                 h0, HL, HL, w_hh0,
                 b_ih0, b_hh0, gates, n, G4H, /*transB=*/1, 0);
        lstm_cell<<<(cellThreads + 255) / 256, 256>>>(gates, h0, c0, cellThreads);
        // layer 1: gates = h0 @ w_ih1^T + h1 @ w_hh1^T + b
        run_gemm(h0, HL, HL, w_ih1,
                 h1, HL, HL, w_hh1,
                 b_ih1, b_hh1, gates, n, G4H, 1, 0);
        lstm_cell<<<(cellThreads + 255) / 256, 256>>>(gates, h1, c1, cellThreads);
    }
    // node features = h1 (layer-1 hidden at last step)

    const int edgeThreads = Etot * GH;
    const int edgeBlocks  = (edgeThreads + 255) / 256;
    const int ndTot = n * GD;

    // ------------- GAT layer 0 (input: h1, K=256) -------------
    run_gemm(h1, HL, HL, g0_wl, nullptr, 0, 0, nullptr, g0_bl, nullptr,
             xl, n, GD, /*transB=*/0, 0);
    run_gemm(h1, HL, HL, g0_wr, nullptr, 0, 0, nullptr, g0_br, nullptr,
             xr, n, GD, 0, 0);
    cudaMemsetAsync(den, 0, (size_t)n * GH * sizeof(float));
    cudaMemsetAsync(gout, 0, (size_t)ndTot * sizeof(float));
    gat_edge_logits<<<edgeBlocks, 256>>>(src, dst, eattr, g0_we, g0_att,
                                         xl, xr, expl, den, E, Etot);
    gat_edge_aggr<<<edgeBlocks, 256>>>(src, dst, xl, expl, den, gout, E, Etot);
    gat_finalize<<<(ndTot + 255) / 256, 256>>>(gout, g0_bias, gin, ndTot);

    // ------------- GAT layer 1 (input: gin, K=512) -------------
    run_gemm(gin, GD, GD, g1_wl, nullptr, 0, 0, nullptr, g1_bl, nullptr,
             xl, n, GD, 0, 0);
    run_gemm(gin, GD, GD, g1_wr, nullptr, 0, 0, nullptr, g1_br, nullptr,
             xr, n, GD, 0, 0);
    cudaMemsetAsync(den, 0, (size_t)n * GH * sizeof(float));
    cudaMemsetAsync(gout, 0, (size_t)ndTot * sizeof(float));
    gat_edge_logits<<<edgeBlocks, 256>>>(src, dst, eattr, g1_we, g1_att,
                                         xl, xr, expl, den, E, Etot);
    gat_edge_aggr<<<edgeBlocks, 256>>>(src, dst, xl, expl, den, gout, E, Etot);
    gat_finalize<<<(ndTot + 255) / 256, 256>>>(gout, g1_bias, gin, ndTot);

    // ------------- fusion MLP -------------
    // fc1: relu( [node | g] @ fc1_w + b ) via dual-A GEMM (concat split)
    run_gemm(h1, HL, HL, fc1_w,
             gin, GD, GD, fc1_w + (size_t)HL * FH,
             fc1_b, nullptr, fc1buf, n, FH, /*transB=*/0, /*act=*/1);
    // fc2: [n,512] @ [512,1]
    gemv_fc2<<<(n * 32 + 255) / 256, 256>>>(fc1buf, fc2_w, fc2_b,
                                            (float*)d_out, n);
}

// round 11
// speedup vs baseline: 1.0017x; 1.0010x over previous
#include <cuda_runtime.h>
#include <cuda_bf16.h>
#include <cstdint>
#include <cstdio>

// Problem constants
#define NN    10000
#define TT    60
#define FF    16
#define HL    256
#define G4H   1024     // 4*HL
#define GH    8
#define GC    64
#define GD    512
#define FH    512
#define EMAX  320000
#define ETOTMAX (EMAX + NN)

// ---------------- device scratch (no allocations allowed) ----------------
__device__ float g_h0[NN * HL];
__device__ float g_c0[NN * HL];
__device__ float g_h1[NN * HL];
__device__ float g_c1[NN * HL];
__device__ float g_gates[NN * G4H];
__device__ float g_xl[NN * GD];
__device__ float g_xr[NN * GD];
__device__ float g_gout[NN * GD];
__device__ float g_gin[NN * GD];
__device__ float g_den[NN * GH];
__device__ float g_expl[ETOTMAX * GH];
__device__ float g_fc1[NN * FH];
__device__ float g_partial[256];
__device__ float g_mean_buf[1];

// ---------------- GEMM: C = A1@op(B1) + A2@op(B2) + bias1 + bias2 --------
// transB=1: B is [M x K] row-major (A @ B^T)   (LSTM weights)
// transB=0: B is [K x M] row-major (A @ B)     (GAT / MLP weights)
// act: 0 none, 1 relu
#define BM 128
#define BN 128
#define BK 8

__global__ __launch_bounds__(256) void gemm_dual(
    const float* __restrict__ A1, int lda1, int K1, const float* __restrict__ B1,
    const float* __restrict__ A2, int lda2, int K2, const float* __restrict__ B2,
    const float* __restrict__ bias1, const float* __restrict__ bias2,
    float* __restrict__ C, int Nr, int M, int transB, int act)
{
    __shared__ float As[BK][BM];
    __shared__ float Bs[BK][BN];

    const int tid = threadIdx.x;
    const int tx = tid & 15;        // 0..15 -> col group of 8
    const int ty = tid >> 4;        // 0..15 -> row group of 8
    const int rowBase = blockIdx.y * BM;
    const int colBase = blockIdx.x * BN;

    float acc[8][8];
#pragma unroll
    for (int i = 0; i < 8; i++)
#pragma unroll
        for (int j = 0; j < 8; j++) acc[i][j] = 0.f;

    for (int phase = 0; phase < 2; phase++) {
        const float* A = phase ? A2 : A1;
        const float* B = phase ? B2 : B1;
        const int K   = phase ? K2 : K1;
        const int lda = phase ? lda2 : lda1;
        for (int k0 = 0; k0 < K; k0 += BK) {
            // load A tile: As[k][m]
            {
                int r  = tid >> 1;
                int kq = (tid & 1) * 4;
                int gr = rowBase + r;
                float4 v = make_float4(0.f, 0.f, 0.f, 0.f);
                if (gr < Nr)
                    v = *(const float4*)(A + (size_t)gr * lda + k0 + kq);
                As[kq + 0][r] = v.x; As[kq + 1][r] = v.y;
                As[kq + 2][r] = v.z; As[kq + 3][r] = v.w;
            }
            // load B tile: Bs[k][n]
            if (transB) {
                int r  = tid >> 1;                 // output col within tile
                int kq = (tid & 1) * 4;
                float4 v = *(const float4*)(B + (size_t)(colBase + r) * K + k0 + kq);
                Bs[kq + 0][r] = v.x; Bs[kq + 1][r] = v.y;
                Bs[kq + 2][r] = v.z; Bs[kq + 3][r] = v.w;
            } else {
                int kk = tid >> 5;                 // 0..7
                int n4 = (tid & 31) * 4;
                float4 v = *(const float4*)(B + (size_t)(k0 + kk) * M + colBase + n4);
                Bs[kk][n4 + 0] = v.x; Bs[kk][n4 + 1] = v.y;
                Bs[kk][n4 + 2] = v.z; Bs[kk][n4 + 3] = v.w;
            }
            __syncthreads();
#pragma unroll
            for (int k = 0; k < BK; k++) {
                float4 a0 = *(const float4*)&As[k][ty * 8];
                float4 a1 = *(const float4*)&As[k][ty * 8 + 4];
                float4 b0 = *(const float4*)&Bs[k][tx * 8];
                float4 b1 = *(const float4*)&Bs[k][tx * 8 + 4];
                float ra[8] = {a0.x, a0.y, a0.z, a0.w, a1.x, a1.y, a1.z, a1.w};
                float rb[8] = {b0.x, b0.y, b0.z, b0.w, b1.x, b1.y, b1.z, b1.w};
#pragma unroll
                for (int i = 0; i < 8; i++)
#pragma unroll
                    for (int j = 0; j < 8; j++)
                        acc[i][j] = fmaf(ra[i], rb[j], acc[i][j]);
            }
            __syncthreads();
        }
    }

#pragma unroll
    for (int i = 0; i < 8; i++) {
        int gr = rowBase + ty * 8 + i;
        if (gr >= Nr) continue;
#pragma unroll
        for (int j = 0; j < 8; j++) {
            int gc = colBase + tx * 8 + j;
            float v = acc[i][j];
            if (bias1) v += bias1[gc];
            if (bias2) v += bias2[gc];
            if (act == 1) v = fmaxf(v, 0.f);
            C[(size_t)gr * M + gc] = v;
        }
    }
}

// ---------------- LSTM cell pointwise -------------------------------------
__global__ void lstm_cell(const float* __restrict__ gates,
                          float* __restrict__ h, float* __restrict__ c, int total)
{
    int idx = blockIdx.x * blockDim.x + threadIdx.x;
    if (idx >= total) return;
    int row = idx >> 8;          // /256
    int j   = idx & 255;
    const float* g = gates + (size_t)row * G4H;
    float gi = g[j], gf = g[j + HL], gg = g[j + 2 * HL], go = g[j + 3 * HL];
    float si = 1.f / (1.f + __expf(-gi));
    float sf = 1.f / (1.f + __expf(-gf));
    float so = 1.f / (1.f + __expf(-go));
    float cn = sf * c[idx] + si * tanhf(gg);
    c[idx] = cn;
    h[idx] = so * tanhf(cn);
}

// ---------------- edge_attr mean (deterministic 2-stage) -------------------
__global__ void reduce_mean1(const float* __restrict__ ea, int E)
{
    __shared__ float s[256];
    int tid = threadIdx.x;
    float acc = 0.f;
    for (int i = blockIdx.x * 256 + tid; i < E; i += 256 * 256) acc += ea[i];
    s[tid] = acc;
    __syncthreads();
    for (int off = 128; off > 0; off >>= 1) {
        if (tid < off) s[tid] += s[tid + off];
        __syncthreads();
    }
    if (tid == 0) g_partial[blockIdx.x] = s[0];
}

__global__ void reduce_mean2(int E)
{
    __shared__ float s[256];
    int tid = threadIdx.x;
    s[tid] = g_partial[tid];
    __syncthreads();
    for (int off = 128; off > 0; off >>= 1) {
        if (tid < off) s[tid] += s[tid + off];
        __syncthreads();
    }
    if (tid == 0) g_mean_buf[0] = s[0] / (float)E;
}

// ---------------- GAT edge pass 1: logits -> exp, accumulate denominator ---
// Softmax computed without max-subtraction: for this data distribution the
// logits are bounded (|logit| < ~30), exp() is safe in fp32, and the result
// is mathematically identical.
__global__ void gat_edge_logits(
    const int* __restrict__ src, const int* __restrict__ dst,
    const float* __restrict__ ea,
    const float* __restrict__ we, const float* __restrict__ att,
    const float* __restrict__ xl, const float* __restrict__ xr,
    float* __restrict__ expl, float* __restrict__ den,
    int E, int Etot)
{
    int idx = blockIdx.x * blockDim.x + threadIdx.x;
    if (idx >= Etot * GH) return;
    int e = idx >> 3;
    int h = idx & 7;
    int s, d; float a;
    if (e < E) { s = src[e]; d = dst[e]; a = ea[e]; }
    else       { s = d = e - E;          a = g_mean_buf[0]; }

    const float4* pl = (const float4*)(xl + (size_t)s * GD + h * GC);
    const float4* pr = (const float4*)(xr + (size_t)d * GD + h * GC);
    const float4* pw = (const float4*)(we + h * GC);
    const float4* pa = (const float4*)(att + h * GC);

    float acc = 0.f;
#pragma unroll
    for (int c4 = 0; c4 < GC / 4; c4++) {
        float4 vl = pl[c4], vr = pr[c4], vw = pw[c4], va = pa[c4];
        float m;
        m = vl.x + vr.x + a * vw.x; m = m > 0.f ? m : 0.2f * m; acc += m * va.x;
        m = vl.y + vr.y + a * vw.y; m = m > 0.f ? m : 0.2f * m; acc += m * va.y;
        m = vl.z + vr.z + a * vw.z; m = m > 0.f ? m : 0.2f * m; acc += m * va.z;
        m = vl.w + vr.w + a * vw.w; m = m > 0.f ? m : 0.2f * m; acc += m * va.w;
    }
    float ex = __expf(acc);
    expl[idx] = ex;
    atomicAdd(&den[d * GH + h], ex);
}

// ---------------- GAT edge pass 2: weighted aggregation --------------------
__global__ void gat_edge_aggr(
    const int* __restrict__ src, const int* __restrict__ dst,
    const float* __restrict__ xl,
    const float* __restrict__ expl, const float* __restrict__ den,
    float* __restrict__ gout,
    int E, int Etot)
{
    int idx = blockIdx.x * blockDim.x + threadIdx.x;
    if (idx >= Etot * GH) return;
    int e = idx >> 3;
    int h = idx & 7;
    int s, d;
    if (e < E) { s = src[e]; d = dst[e]; }
    else       { s = d = e - E; }

    float alpha = expl[idx] / den[d * GH + h];
    const float4* pl = (const float4*)(xl + (size_t)s * GD + h * GC);
    float* po = gout + (size_t)d * GD + h * GC;
#pragma unroll
    for (int c4 = 0; c4 < GC / 4; c4++) {
        float4 v = pl[c4];
        atomicAdd(&po[c4 * 4 + 0], v.x * alpha);
        atomicAdd(&po[c4 * 4 + 1], v.y * alpha);
        atomicAdd(&po[c4 * 4 + 2], v.z * alpha);
        atomicAdd(&po[c4 * 4 + 3], v.w * alpha);
    }
}

// ---------------- GAT finalize: +bias, ELU ---------------------------------
__global__ void gat_finalize(const float* __restrict__ gout,
                             const float* __restrict__ bias,
                             float* __restrict__ out, int total)
{
    int idx = blockIdx.x * blockDim.x + threadIdx.x;
    if (idx >= total) return;
    float v = gout[idx] + bias[idx & (GD - 1)];
    out[idx] = v > 0.f ? v : expm1f(v);
}

// ---------------- fc2 GEMV -------------------------------------------------
__global__ void gemv_fc2(const float* __restrict__ hbuf,
                         const float* __restrict__ w, const float* __restrict__ b,
                         float* __restrict__ out, int n)
{
    int gw = (blockIdx.x * blockDim.x + threadIdx.x) >> 5;
    int lane = threadIdx.x & 31;
    if (gw >= n) return;
    const float* row = hbuf + (size_t)gw * FH;
    float acc = 0.f;
#pragma unroll
    for (int k = lane; k < FH; k += 32) acc += row[k] * w[k];
#pragma unroll
    for (int off = 16; off > 0; off >>= 1) acc += __shfl_xor_sync(0xffffffffu, acc, off);
    if (lane == 0) out[gw] = acc + b[0];
}

// ---------------- host orchestration ---------------------------------------
static inline void run_gemm(const float* A1, int lda1, int K1, const float* B1,
                            const float* A2, int lda2, int K2, const float* B2,
                            const float* bias1, const float* bias2,
                            float* C, int Nr, int M, int transB, int act)
{
    dim3 grid((M + BN - 1) / BN, (Nr + BM - 1) / BM);
    gemm_dual<<<grid, 256>>>(A1, lda1, K1, B1, A2, lda2, K2, B2,
                             bias1, bias2, C, Nr, M, transB, act);
}

extern "C" void kernel_launch(void* const* d_in, const int* in_sizes, int n_in,
                              void* d_out, int out_size)
{
    const float* x_seq  = (const float*)d_in[0];
    const int*   eidx   = (const int*)  d_in[1];
    const float* eattr  = (const float*)d_in[2];
    const float* w_ih0  = (const float*)d_in[3];
    const float* w_hh0  = (const float*)d_in[4];
    const float* b_ih0  = (const float*)d_in[5];
    const float* b_hh0  = (const float*)d_in[6];
    const float* w_ih1  = (const float*)d_in[7];
    const float* w_hh1  = (const float*)d_in[8];
    const float* b_ih1  = (const float*)d_in[9];
    const float* b_hh1  = (const float*)d_in[10];
    const float* g0_wl  = (const float*)d_in[11];
    const float* g0_bl  = (const float*)d_in[12];
    const float* g0_wr  = (const float*)d_in[13];
    const float* g0_br  = (const float*)d_in[14];
    const float* g0_we  = (const float*)d_in[15];
    const float* g0_att = (const float*)d_in[16];
    const float* g0_bias= (const float*)d_in[17];
    const float* g1_wl  = (const float*)d_in[18];
    const float* g1_bl  = (const float*)d_in[19];
    const float* g1_wr  = (const float*)d_in[20];
    const float* g1_br  = (const float*)d_in[21];
    const float* g1_we  = (const float*)d_in[22];
    const float* g1_att = (const float*)d_in[23];
    const float* g1_bias= (const float*)d_in[24];
    const float* fc1_w  = (const float*)d_in[25];
    const float* fc1_b  = (const float*)d_in[26];
    const float* fc2_w  = (const float*)d_in[27];
    const float* fc2_b  = (const float*)d_in[28];

    const int n = in_sizes[0] / (TT * FF);
    const int E = in_sizes[2];
    const int Etot = E + n;
    const int* src = eidx;
    const int* dst = eidx + E;

    float *h0, *c0, *h1, *c1, *gates, *xl, *xr, *gout, *gin, *den, *expl, *fc1buf;
    cudaGetSymbolAddress((void**)&h0, g_h0);
    cudaGetSymbolAddress((void**)&c0, g_c0);
    cudaGetSymbolAddress((void**)&h1, g_h1);
    cudaGetSymbolAddress((void**)&c1, g_c1);
    cudaGetSymbolAddress((void**)&gates, g_gates);
    cudaGetSymbolAddress((void**)&xl, g_xl);
    cudaGetSymbolAddress((void**)&xr, g_xr);
    cudaGetSymbolAddress((void**)&gout, g_gout);
    cudaGetSymbolAddress((void**)&gin, g_gin);
    cudaGetSymbolAddress((void**)&den, g_den);
    cudaGetSymbolAddress((void**)&expl, g_expl);
    cudaGetSymbolAddress((void**)&fc1buf, g_fc1);

    // init states
    cudaMemsetAsync(h0, 0, (size_t)n * HL * sizeof(float));
    cudaMemsetAsync(c0, 0, (size_t)n * HL * sizeof(float));
    cudaMemsetAsync(h1, 0, (size_t)n * HL * sizeof(float));
    cudaMemsetAsync(c1, 0, (size_t)n * HL * sizeof(float));

    // edge_attr mean (for self-loop fill)
    reduce_mean1<<<256, 256>>>(eattr, E);
    reduce_mean2<<<1, 256>>>(E);

    // ------------- LSTM: 2 layers interleaved over 60 steps -------------
    const int cellThreads = n * HL;
    for (int t = 0; t < TT; t++) {
        // layer 0: gates = x_t @ w_ih0^T + h0 @ w_hh0^T + b
        run_gemm(x_seq + (size_t)t * FF, TT * FF, FF, w_ih0,
                 h0, HL, HL, w_hh0,
                 b_ih0, b_hh0, gates, n, G4H, /*transB=*/1, 0);
        lstm_cell<<<(cellThreads + 255) / 256, 256>>>(gates, h0, c0, cellThreads);
        // layer 1: gates = h0 @ w_ih1^T + h1 @ w_hh1^T + b
        run_gemm(h0, HL, HL, w_ih1,
                 h1, HL, HL, w_hh1,
                 b_ih1, b_hh1, gates, n, G4H, 1, 0);
        lstm_cell<<<(cellThreads + 255) / 256, 256>>>(gates, h1, c1, cellThreads);
    }
    // node features = h1 (layer-1 hidden at last step)

    const int edgeThreads = Etot * GH;
    const int edgeBlocks  = (edgeThreads + 255) / 256;
    const int ndTot = n * GD;

    // ------------- GAT layer 0 (input: h1, K=256) -------------
    run_gemm(h1, HL, HL, g0_wl, nullptr, 0, 0, nullptr, g0_bl, nullptr,
             xl, n, GD, /*transB=*/0, 0);
    run_gemm(h1, HL, HL, g0_wr, nullptr, 0, 0, nullptr, g0_br, nullptr,
             xr, n, GD, 0, 0);
    cudaMemsetAsync(den, 0, (size_t)n * GH * sizeof(float));
    cudaMemsetAsync(gout, 0, (size_t)ndTot * sizeof(float));
    gat_edge_logits<<<edgeBlocks, 256>>>(src, dst, eattr, g0_we, g0_att,
                                         xl, xr, expl, den, E, Etot);
    gat_edge_aggr<<<edgeBlocks, 256>>>(src, dst, xl, expl, den, gout, E, Etot);
    gat_finalize<<<(ndTot + 255) / 256, 256>>>(gout, g0_bias, gin, ndTot);

    // ------------- GAT layer 1 (input: gin, K=512) -------------
    run_gemm(gin, GD, GD, g1_wl, nullptr, 0, 0, nullptr, g1_bl, nullptr,
             xl, n, GD, 0, 0);
    run_gemm(gin, GD, GD, g1_wr, nullptr, 0, 0, nullptr, g1_br, nullptr,
             xr, n, GD, 0, 0);
    cudaMemsetAsync(den, 0, (size_t)n * GH * sizeof(float));
    cudaMemsetAsync(gout, 0, (size_t)ndTot * sizeof(float));
    gat_edge_logits<<<edgeBlocks, 256>>>(src, dst, eattr, g1_we, g1_att,
                                         xl, xr, expl, den, E, Etot);
    gat_edge_aggr<<<edgeBlocks, 256>>>(src, dst, xl, expl, den, gout, E, Etot);
    gat_finalize<<<(ndTot + 255) / 256, 256>>>(gout, g1_bias, gin, ndTot);

    // ------------- fusion MLP -------------
    // fc1: relu( [node | g] @ fc1_w + b ) via dual-A GEMM (concat split)
    run_gemm(h1, HL, HL, fc1_w,
             gin, GD, GD, fc1_w + (size_t)HL * FH,
             fc1_b, nullptr, fc1buf, n, FH, /*transB=*/0, /*act=*/1);
    // fc2: [n,512] @ [512,1]
    gemv_fc2<<<(n * 32 + 255) / 256, 256>>>(fc1buf, fc2_w, fc2_b,
                                            (float*)d_out, n);
}

// round 12
// speedup vs baseline: 1.2443x; 1.2421x over previous
#include <cuda_runtime.h>
#include <cuda_bf16.h>
#include <cstdint>
#include <cstdio>

// Problem constants
#define NN    10000
#define TT    60
#define FF    16
#define HL    256
#define G4H   1024     // 4*HL
#define GH    8
#define GC    64
#define GD    512
#define FH    512
#define EMAX  320000
#define ETOTMAX (EMAX + NN)

// ---------------- device scratch (no allocations allowed) ----------------
__device__ float g_h0[NN * HL];
__device__ float g_c0[NN * HL];
__device__ float g_h1[NN * HL];
__device__ float g_c1[NN * HL];
__device__ float g_gates[NN * G4H];
__device__ float g_xl[NN * GD];
__device__ float g_xr[NN * GD];
__device__ float g_gout[NN * GD];
__device__ float g_gin[NN * GD];
__device__ float g_den[NN * GH];
__device__ float g_expl[ETOTMAX * GH];
__device__ float g_fc1[NN * FH];
__device__ float g_partial[256];
__device__ float g_mean_buf[1];

// hi/lo tf32 splits of LSTM weights (built once per launch)
__device__ float g_wih0hi[G4H * FF],  g_wih0lo[G4H * FF];
__device__ float g_whh0hi[G4H * HL],  g_whh0lo[G4H * HL];
__device__ float g_wih1hi[G4H * HL],  g_wih1lo[G4H * HL];
__device__ float g_whh1hi[G4H * HL],  g_whh1lo[G4H * HL];

// ---------------- tf32 helpers ---------------------------------------------
__device__ __forceinline__ uint32_t f2tf32(float x) {
    uint32_t r;
    asm("cvt.rna.tf32.f32 %0, %1;" : "=r"(r) : "f"(x));
    return r;
}

__device__ __forceinline__ void mma_tf32(
    float& c0, float& c1, float& c2, float& c3,
    uint32_t a0, uint32_t a1, uint32_t a2, uint32_t a3,
    uint32_t b0, uint32_t b1)
{
    asm volatile(
        "mma.sync.aligned.m16n8k8.row.col.f32.tf32.tf32.f32 "
        "{%0,%1,%2,%3}, {%4,%5,%6,%7}, {%8,%9}, {%0,%1,%2,%3};"
        : "+f"(c0), "+f"(c1), "+f"(c2), "+f"(c3)
        : "r"(a0), "r"(a1), "r"(a2), "r"(a3), "r"(b0), "r"(b1));
}

// ---------------- weight split kernel ---------------------------------------
__global__ void split_tf32(const float* __restrict__ w,
                           float* __restrict__ hi, float* __restrict__ lo, int n)
{
    int i = blockIdx.x * 256 + threadIdx.x;
    if (i >= n) return;
    float v = w[i];
    float fh = __uint_as_float(f2tf32(v));
    hi[i] = fh;
    lo[i] = __uint_as_float(f2tf32(v - fh));
}

// ---------------- LSTM GEMM: tensor-core tf32 (3xTF32 = fp32 precision) ----
// C[Nr x 1024] = A1 @ B1^T + A2 @ B2^T + bias1 + bias2
// B given as pre-split hi/lo, layout [1024 x K] row-major (== col-major B for mma).
// Tile: BM=128 x BN=128 x BK=16, 8 warps, each warp 64x32.
#define LBM 128
#define LBN 128
#define LBK 16
#define LPAD 8

__global__ __launch_bounds__(256) void lstm_gemm_tf32(
    const float* __restrict__ A1, int lda1, int K1,
    const float* __restrict__ B1hi, const float* __restrict__ B1lo,
    const float* __restrict__ A2, int lda2, int K2,
    const float* __restrict__ B2hi, const float* __restrict__ B2lo,
    const float* __restrict__ bias1, const float* __restrict__ bias2,
    float* __restrict__ C, int Nr)
{
    __shared__ float sAhi[LBK][LBM + LPAD];
    __shared__ float sAlo[LBK][LBM + LPAD];
    __shared__ float sBhi[LBK][LBN + LPAD];
    __shared__ float sBlo[LBK][LBN + LPAD];

    const int tid  = threadIdx.x;
    const int lane = tid & 31;
    const int warp = tid >> 5;
    const int grp  = lane >> 2;   // 0..7
    const int tig  = lane & 3;    // 0..3
    const int wm   = (warp & 1) * 64;   // warp row offset (2 in M)
    const int wn   = (warp >> 1) * 32;  // warp col offset (4 in N)
    const int rowBase = blockIdx.y * LBM;
    const int colBase = blockIdx.x * LBN;

    float acc[4][4][4];
#pragma unroll
    for (int i = 0; i < 4; i++)
#pragma unroll
        for (int j = 0; j < 4; j++)
#pragma unroll
            for (int q = 0; q < 4; q++) acc[i][j][q] = 0.f;

    for (int phase = 0; phase < 2; phase++) {
        const float* A   = phase ? A2 : A1;
        const float* Bhi = phase ? B2hi : B1hi;
        const float* Blo = phase ? B2lo : B1lo;
        const int K      = phase ? K2 : K1;
        const int lda    = phase ? lda2 : lda1;
        if (K == 0) continue;

        for (int k0 = 0; k0 < K; k0 += LBK) {
            // ---- load + split A tile: sA[k][m] (transposed stage) ----
#pragma unroll
            for (int j = 0; j < 2; j++) {
                int fidx = tid * 2 + j;        // 0..511 float4 slots
                int r    = fidx >> 2;          // row 0..127
                int c4   = (fidx & 3) * 4;     // k offset 0,4,8,12
                int gr   = rowBase + r;
                float4 v = make_float4(0.f, 0.f, 0.f, 0.f);
                if (gr < Nr)
                    v = *(const float4*)(A + (size_t)gr * lda + k0 + c4);
                float vv[4] = {v.x, v.y, v.z, v.w};
#pragma unroll
                for (int q = 0; q < 4; q++) {
                    float fh = __uint_as_float(f2tf32(vv[q]));
                    sAhi[c4 + q][r] = fh;
                    sAlo[c4 + q][r] = __uint_as_float(f2tf32(vv[q] - fh));
                }
            }
            // ---- load B tiles (pre-split): sB[k][n] ----
#pragma unroll
            for (int j = 0; j < 2; j++) {
                int fidx = tid * 2 + j;
                int r    = fidx >> 2;          // output col n within tile
                int c4   = (fidx & 3) * 4;
                size_t off = (size_t)(colBase + r) * K + k0 + c4;
                float4 vh = *(const float4*)(Bhi + off);
                float4 vl = *(const float4*)(Blo + off);
                sBhi[c4 + 0][r] = vh.x; sBhi[c4 + 1][r] = vh.y;
                sBhi[c4 + 2][r] = vh.z; sBhi[c4 + 3][r] = vh.w;
                sBlo[c4 + 0][r] = vl.x; sBlo[c4 + 1][r] = vl.y;
                sBlo[c4 + 2][r] = vl.z; sBlo[c4 + 3][r] = vl.w;
            }
            __syncthreads();

            // ---- compute: 2 k-steps of 8 ----
#pragma unroll
            for (int kk = 0; kk < LBK; kk += 8) {
                uint32_t bh0[4], bh1[4], bl0[4], bl1[4];
#pragma unroll
                for (int nt = 0; nt < 4; nt++) {
                    int n0 = wn + nt * 8 + grp;
                    bh0[nt] = __float_as_uint(sBhi[kk + tig][n0]);
                    bh1[nt] = __float_as_uint(sBhi[kk + 4 + tig][n0]);
                    bl0[nt] = __float_as_uint(sBlo[kk + tig][n0]);
                    bl1[nt] = __float_as_uint(sBlo[kk + 4 + tig][n0]);
                }
#pragma unroll
                for (int mt = 0; mt < 4; mt++) {
                    int m0 = wm + mt * 16 + grp;
                    uint32_t ah0 = __float_as_uint(sAhi[kk + tig][m0]);
                    uint32_t ah1 = __float_as_uint(sAhi[kk + tig][m0 + 8]);
                    uint32_t ah2 = __float_as_uint(sAhi[kk + 4 + tig][m0]);
                    uint32_t ah3 = __float_as_uint(sAhi[kk + 4 + tig][m0 + 8]);
                    uint32_t al0 = __float_as_uint(sAlo[kk + tig][m0]);
                    uint32_t al1 = __float_as_uint(sAlo[kk + tig][m0 + 8]);
                    uint32_t al2 = __float_as_uint(sAlo[kk + 4 + tig][m0]);
                    uint32_t al3 = __float_as_uint(sAlo[kk + 4 + tig][m0 + 8]);
#pragma unroll
                    for (int nt = 0; nt < 4; nt++) {
                        float* c = acc[mt][nt];
                        mma_tf32(c[0], c[1], c[2], c[3],
                                 ah0, ah1, ah2, ah3, bh0[nt], bh1[nt]);
                        mma_tf32(c[0], c[1], c[2], c[3],
                                 ah0, ah1, ah2, ah3, bl0[nt], bl1[nt]);
                        mma_tf32(c[0], c[1], c[2], c[3],
                                 al0, al1, al2, al3, bh0[nt], bh1[nt]);
                    }
                }
            }
            __syncthreads();
        }
    }

    // ---- epilogue: + biases, write gates ----
#pragma unroll
    for (int mt = 0; mt < 4; mt++) {
        int r0 = rowBase + wm + mt * 16 + grp;
#pragma unroll
        for (int nt = 0; nt < 4; nt++) {
            int c0i = colBase + wn + nt * 8 + 2 * tig;
            float bsum0 = bias1[c0i] + bias2[c0i];
            float bsum1 = bias1[c0i + 1] + bias2[c0i + 1];
            if (r0 < Nr) {
                C[(size_t)r0 * G4H + c0i]     = acc[mt][nt][0] + bsum0;
                C[(size_t)r0 * G4H + c0i + 1] = acc[mt][nt][1] + bsum1;
            }
            if (r0 + 8 < Nr) {
                C[(size_t)(r0 + 8) * G4H + c0i]     = acc[mt][nt][2] + bsum0;
                C[(size_t)(r0 + 8) * G4H + c0i + 1] = acc[mt][nt][3] + bsum1;
            }
        }
    }
}

// ---------------- GEMM (SIMT fp32) for GAT/MLP: C = A1@op(B1)+A2@op(B2)+b --
#define BM 128
#define BN 128
#define BK 8

__global__ __launch_bounds__(256) void gemm_dual(
    const float* __restrict__ A1, int lda1, int K1, const float* __restrict__ B1,
    const float* __restrict__ A2, int lda2, int K2, const float* __restrict__ B2,
    const float* __restrict__ bias1, const float* __restrict__ bias2,
    float* __restrict__ C, int Nr, int M, int transB, int act)
{
    __shared__ float As[BK][BM];
    __shared__ float Bs[BK][BN];

    const int tid = threadIdx.x;
    const int tx = tid & 15;
    const int ty = tid >> 4;
    const int rowBase = blockIdx.y * BM;
    const int colBase = blockIdx.x * BN;

    float acc[8][8];
#pragma unroll
    for (int i = 0; i < 8; i++)
#pragma unroll
        for (int j = 0; j < 8; j++) acc[i][j] = 0.f;

    for (int phase = 0; phase < 2; phase++) {
        const float* A = phase ? A2 : A1;
        const float* B = phase ? B2 : B1;
        const int K   = phase ? K2 : K1;
        const int lda = phase ? lda2 : lda1;
        for (int k0 = 0; k0 < K; k0 += BK) {
            {
                int r  = tid >> 1;
                int kq = (tid & 1) * 4;
                int gr = rowBase + r;
                float4 v = make_float4(0.f, 0.f, 0.f, 0.f);
                if (gr < Nr)
                    v = *(const float4*)(A + (size_t)gr * lda + k0 + kq);
                As[kq + 0][r] = v.x; As[kq + 1][r] = v.y;
                As[kq + 2][r] = v.z; As[kq + 3][r] = v.w;
            }
            if (transB) {
                int r  = tid >> 1;
                int kq = (tid & 1) * 4;
                float4 v = *(const float4*)(B + (size_t)(colBase + r) * K + k0 + kq);
                Bs[kq + 0][r] = v.x; Bs[kq + 1][r] = v.y;
                Bs[kq + 2][r] = v.z; Bs[kq + 3][r] = v.w;
            } else {
                int kk = tid >> 5;
                int n4 = (tid & 31) * 4;
                float4 v = *(const float4*)(B + (size_t)(k0 + kk) * M + colBase + n4);
                Bs[kk][n4 + 0] = v.x; Bs[kk][n4 + 1] = v.y;
                Bs[kk][n4 + 2] = v.z; Bs[kk][n4 + 3] = v.w;
            }
            __syncthreads();
#pragma unroll
            for (int k = 0; k < BK; k++) {
                float4 a0 = *(const float4*)&As[k][ty * 8];
                float4 a1 = *(const float4*)&As[k][ty * 8 + 4];
                float4 b0 = *(const float4*)&Bs[k][tx * 8];
                float4 b1 = *(const float4*)&Bs[k][tx * 8 + 4];
                float ra[8] = {a0.x, a0.y, a0.z, a0.w, a1.x, a1.y, a1.z, a1.w};
                float rb[8] = {b0.x, b0.y, b0.z, b0.w, b1.x, b1.y, b1.z, b1.w};
#pragma unroll
                for (int i = 0; i < 8; i++)
#pragma unroll
                    for (int j = 0; j < 8; j++)
                        acc[i][j] = fmaf(ra[i], rb[j], acc[i][j]);
            }
            __syncthreads();
        }
    }

#pragma unroll
    for (int i = 0; i < 8; i++) {
        int gr = rowBase + ty * 8 + i;
        if (gr >= Nr) continue;
#pragma unroll
        for (int j = 0; j < 8; j++) {
            int gc = colBase + tx * 8 + j;
            float v = acc[i][j];
            if (bias1) v += bias1[gc];
            if (bias2) v += bias2[gc];
            if (act == 1) v = fmaxf(v, 0.f);
            C[(size_t)gr * M + gc] = v;
        }
    }
}

// ---------------- LSTM cell pointwise -------------------------------------
__global__ void lstm_cell(const float* __restrict__ gates,
                          float* __restrict__ h, float* __restrict__ c, int total)
{
    int idx = blockIdx.x * blockDim.x + threadIdx.x;
    if (idx >= total) return;
    int row = idx >> 8;
    int j   = idx & 255;
    const float* g = gates + (size_t)row * G4H;
    float gi = g[j], gf = g[j + HL], gg = g[j + 2 * HL], go = g[j + 3 * HL];
    float si = 1.f / (1.f + __expf(-gi));
    float sf = 1.f / (1.f + __expf(-gf));
    float so = 1.f / (1.f + __expf(-go));
    float cn = sf * c[idx] + si * tanhf(gg);
    c[idx] = cn;
    h[idx] = so * tanhf(cn);
}

// ---------------- edge_attr mean (deterministic 2-stage) -------------------
__global__ void reduce_mean1(const float* __restrict__ ea, int E)
{
    __shared__ float s[256];
    int tid = threadIdx.x;
    float acc = 0.f;
    for (int i = blockIdx.x * 256 + tid; i < E; i += 256 * 256) acc += ea[i];
    s[tid] = acc;
    __syncthreads();
    for (int off = 128; off > 0; off >>= 1) {
        if (tid < off) s[tid] += s[tid + off];
        __syncthreads();
    }
    if (tid == 0) g_partial[blockIdx.x] = s[0];
}

__global__ void reduce_mean2(int E)
{
    __shared__ float s[256];
    int tid = threadIdx.x;
    s[tid] = g_partial[tid];
    __syncthreads();
    for (int off = 128; off > 0; off >>= 1) {
        if (tid < off) s[tid] += s[tid + off];
        __syncthreads();
    }
    if (tid == 0) g_mean_buf[0] = s[0] / (float)E;
}

// ---------------- GAT edge pass 1: logits -> exp, accumulate denominator ---
__global__ void gat_edge_logits(
    const int* __restrict__ src, const int* __restrict__ dst,
    const float* __restrict__ ea,
    const float* __restrict__ we, const float* __restrict__ att,
    const float* __restrict__ xl, const float* __restrict__ xr,
    float* __restrict__ expl, float* __restrict__ den,
    int E, int Etot)
{
    int idx = blockIdx.x * blockDim.x + threadIdx.x;
    if (idx >= Etot * GH) return;
    int e = idx >> 3;
    int h = idx & 7;
    int s, d; float a;
    if (e < E) { s = src[e]; d = dst[e]; a = ea[e]; }
    else       { s = d = e - E;          a = g_mean_buf[0]; }

    const float4* pl = (const float4*)(xl + (size_t)s * GD + h * GC);
    const float4* pr = (const float4*)(xr + (size_t)d * GD + h * GC);
    const float4* pw = (const float4*)(we + h * GC);
    const float4* pa = (const float4*)(att + h * GC);

    float acc = 0.f;
#pragma unroll
    for (int c4 = 0; c4 < GC / 4; c4++) {
        float4 vl = pl[c4], vr = pr[c4], vw = pw[c4], va = pa[c4];
        float m;
        m = vl.x + vr.x + a * vw.x; m = m > 0.f ? m : 0.2f * m; acc += m * va.x;
        m = vl.y + vr.y + a * vw.y; m = m > 0.f ? m : 0.2f * m; acc += m * va.y;
        m = vl.z + vr.z + a * vw.z; m = m > 0.f ? m : 0.2f * m; acc += m * va.z;
        m = vl.w + vr.w + a * vw.w; m = m > 0.f ? m : 0.2f * m; acc += m * va.w;
    }
    float ex = __expf(acc);
    expl[idx] = ex;
    atomicAdd(&den[d * GH + h], ex);
}

// ---------------- GAT edge pass 2: weighted aggregation --------------------
__global__ void gat_edge_aggr(
    const int* __restrict__ src, const int* __restrict__ dst,
    const float* __restrict__ xl,
    const float* __restrict__ expl, const float* __restrict__ den,
    float* __restrict__ gout,
    int E, int Etot)
{
    int idx = blockIdx.x * blockDim.x + threadIdx.x;
    if (idx >= Etot * GH) return;
    int e = idx >> 3;
    int h = idx & 7;
    int s, d;
    if (e < E) { s = src[e]; d = dst[e]; }
    else       { s = d = e - E; }

    float alpha = expl[idx] / den[d * GH + h];
    const float4* pl = (const float4*)(xl + (size_t)s * GD + h * GC);
    float* po = gout + (size_t)d * GD + h * GC;
#pragma unroll
    for (int c4 = 0; c4 < GC / 4; c4++) {
        float4 v = pl[c4];
        atomicAdd(&po[c4 * 4 + 0], v.x * alpha);
        atomicAdd(&po[c4 * 4 + 1], v.y * alpha);
        atomicAdd(&po[c4 * 4 + 2], v.z * alpha);
        atomicAdd(&po[c4 * 4 + 3], v.w * alpha);
    }
}

// ---------------- GAT finalize: +bias, ELU ---------------------------------
__global__ void gat_finalize(const float* __restrict__ gout,
                             const float* __restrict__ bias,
                             float* __restrict__ out, int total)
{
    int idx = blockIdx.x * blockDim.x + threadIdx.x;
    if (idx >= total) return;
    float v = gout[idx] + bias[idx & (GD - 1)];
    out[idx] = v > 0.f ? v : expm1f(v);
}

// ---------------- fc2 GEMV -------------------------------------------------
__global__ void gemv_fc2(const float* __restrict__ hbuf,
                         const float* __restrict__ w, const float* __restrict__ b,
                         float* __restrict__ out, int n)
{
    int gw = (blockIdx.x * blockDim.x + threadIdx.x) >> 5;
    int lane = threadIdx.x & 31;
    if (gw >= n) return;
    const float* row = hbuf + (size_t)gw * FH;
    float acc = 0.f;
#pragma unroll
    for (int k = lane; k < FH; k += 32) acc += row[k] * w[k];
#pragma unroll
    for (int off = 16; off > 0; off >>= 1) acc += __shfl_xor_sync(0xffffffffu, acc, off);
    if (lane == 0) out[gw] = acc + b[0];
}

// ---------------- host orchestration ---------------------------------------
static inline void run_gemm(const float* A1, int lda1, int K1, const float* B1,
                            const float* A2, int lda2, int K2, const float* B2,
                            const float* bias1, const float* bias2,
                            float* C, int Nr, int M, int transB, int act)
{
    dim3 grid((M + BN - 1) / BN, (Nr + BM - 1) / BM);
    gemm_dual<<<grid, 256>>>(A1, lda1, K1, B1, A2, lda2, K2, B2,
                             bias1, bias2, C, Nr, M, transB, act);
}

extern "C" void kernel_launch(void* const* d_in, const int* in_sizes, int n_in,
                              void* d_out, int out_size)
{
    const float* x_seq  = (const float*)d_in[0];
    const int*   eidx   = (const int*)  d_in[1];
    const float* eattr  = (const float*)d_in[2];
    const float* w_ih0  = (const float*)d_in[3];
    const float* w_hh0  = (const float*)d_in[4];
    const float* b_ih0  = (const float*)d_in[5];
    const float* b_hh0  = (const float*)d_in[6];
    const float* w_ih1  = (const float*)d_in[7];
    const float* w_hh1  = (const float*)d_in[8];
    const float* b_ih1  = (const float*)d_in[9];
    const float* b_hh1  = (const float*)d_in[10];
    const float* g0_wl  = (const float*)d_in[11];
    const float* g0_bl  = (const float*)d_in[12];
    const float* g0_wr  = (const float*)d_in[13];
    const float* g0_br  = (const float*)d_in[14];
    const float* g0_we  = (const float*)d_in[15];
    const float* g0_att = (const float*)d_in[16];
    const float* g0_bias= (const float*)d_in[17];
    const float* g1_wl  = (const float*)d_in[18];
    const float* g1_bl  = (const float*)d_in[19];
    const float* g1_wr  = (const float*)d_in[20];
    const float* g1_br  = (const float*)d_in[21];
    const float* g1_we  = (const float*)d_in[22];
    const float* g1_att = (const float*)d_in[23];
    const float* g1_bias= (const float*)d_in[24];
    const float* fc1_w  = (const float*)d_in[25];
    const float* fc1_b  = (const float*)d_in[26];
    const float* fc2_w  = (const float*)d_in[27];
    const float* fc2_b  = (const float*)d_in[28];

    const int n = in_sizes[0] / (TT * FF);
    const int E = in_sizes[2];
    const int Etot = E + n;
    const int* src = eidx;
    const int* dst = eidx + E;

    float *h0, *c0, *h1, *c1, *gates, *xl, *xr, *gout, *gin, *den, *fc1buf;
    float *wih0hi, *wih0lo, *whh0hi, *whh0lo, *wih1hi, *wih1lo, *whh1hi, *whh1lo;
    cudaGetSymbolAddress((void**)&h0, g_h0);
    cudaGetSymbolAddress((void**)&c0, g_c0);
    cudaGetSymbolAddress((void**)&h1, g_h1);
    cudaGetSymbolAddress((void**)&c1, g_c1);
    cudaGetSymbolAddress((void**)&gates, g_gates);
    cudaGetSymbolAddress((void**)&xl, g_xl);
    cudaGetSymbolAddress((void**)&xr, g_xr);
    cudaGetSymbolAddress((void**)&gout, g_gout);
    cudaGetSymbolAddress((void**)&gin, g_gin);
    cudaGetSymbolAddress((void**)&den, g_den);
    cudaGetSymbolAddress((void**)&fc1buf, g_fc1);
    cudaGetSymbolAddress((void**)&wih0hi, g_wih0hi);
    cudaGetSymbolAddress((void**)&wih0lo, g_wih0lo);
    cudaGetSymbolAddress((void**)&whh0hi, g_whh0hi);
    cudaGetSymbolAddress((void**)&whh0lo, g_whh0lo);
    cudaGetSymbolAddress((void**)&wih1hi, g_wih1hi);
    cudaGetSymbolAddress((void**)&wih1lo, g_wih1lo);
    cudaGetSymbolAddress((void**)&whh1hi, g_whh1hi);
    cudaGetSymbolAddress((void**)&whh1lo, g_whh1lo);

    // init states
    cudaMemsetAsync(h0, 0, (size_t)n * HL * sizeof(float));
    cudaMemsetAsync(c0, 0, (size_t)n * HL * sizeof(float));
    cudaMemsetAsync(h1, 0, (size_t)n * HL * sizeof(float));
    cudaMemsetAsync(c1, 0, (size_t)n * HL * sizeof(float));

    // edge_attr mean (for self-loop fill)
    reduce_mean1<<<256, 256>>>(eattr, E);
    reduce_mean2<<<1, 256>>>(E);

    // hi/lo tf32 splits of LSTM weights
    split_tf32<<<(G4H * FF + 255) / 256, 256>>>(w_ih0, wih0hi, wih0lo, G4H * FF);
    split_tf32<<<(G4H * HL + 255) / 256, 256>>>(w_hh0, whh0hi, whh0lo, G4H * HL);
    split_tf32<<<(G4H * HL + 255) / 256, 256>>>(w_ih1, wih1hi, wih1lo, G4H * HL);
    split_tf32<<<(G4H * HL + 255) / 256, 256>>>(w_hh1, whh1hi, whh1lo, G4H * HL);

    // ------------- LSTM: 2 layers interleaved over 60 steps -------------
    const int cellThreads = n * HL;
    dim3 lgrid(G4H / LBN, (n + LBM - 1) / LBM);
    for (int t = 0; t < TT; t++) {
        // layer 0: gates = x_t @ w_ih0^T + h0 @ w_hh0^T + b
        lstm_gemm_tf32<<<lgrid, 256>>>(
            x_seq + (size_t)t * FF, TT * FF, FF, wih0hi, wih0lo,
            h0, HL, HL, whh0hi, whh0lo,
            b_ih0, b_hh0, gates, n);
        lstm_cell<<<(cellThreads + 255) / 256, 256>>>(gates, h0, c0, cellThreads);
        // layer 1: gates = h0 @ w_ih1^T + h1 @ w_hh1^T + b
        lstm_gemm_tf32<<<lgrid, 256>>>(
            h0, HL, HL, wih1hi, wih1lo,
            h1, HL, HL, whh1hi, whh1lo,
            b_ih1, b_hh1, gates, n);
        lstm_cell<<<(cellThreads + 255) / 256, 256>>>(gates, h1, c1, cellThreads);
    }
    // node features = h1 (layer-1 hidden at last step)

    const int edgeThreads = Etot * GH;
    const int edgeBlocks  = (edgeThreads + 255) / 256;
    const int ndTot = n * GD;

    // ------------- GAT layer 0 (input: h1, K=256) -------------
    run_gemm(h1, HL, HL, g0_wl, nullptr, 0, 0, nullptr, g0_bl, nullptr,
             xl, n, GD, /*transB=*/0, 0);
    run_gemm(h1, HL, HL, g0_wr, nullptr, 0, 0, nullptr, g0_br, nullptr,
             xr, n, GD, 0, 0);
    cudaMemsetAsync(den, 0, (size_t)n * GH * sizeof(float));
    cudaMemsetAsync(gout, 0, (size_t)ndTot * sizeof(float));
    gat_edge_logits<<<edgeBlocks, 256>>>(src, dst, eattr, g0_we, g0_att,
                                         xl, xr, g_expl, den, E, Etot);
    gat_edge_aggr<<<edgeBlocks, 256>>>(src, dst, xl, g_expl, den, gout, E, Etot);
    gat_finalize<<<(ndTot + 255) / 256, 256>>>(gout, g0_bias, gin, ndTot);

    // ------------- GAT layer 1 (input: gin, K=512) -------------
    run_gemm(gin, GD, GD, g1_wl, nullptr, 0, 0, nullptr, g1_bl, nullptr,
             xl, n, GD, 0, 0);
    run_gemm(gin, GD, GD, g1_wr, nullptr, 0, 0, nullptr, g1_br, nullptr,
             xr, n, GD, 0, 0);
    cudaMemsetAsync(den, 0, (size_t)n * GH * sizeof(float));
    cudaMemsetAsync(gout, 0, (size_t)ndTot * sizeof(float));
    gat_edge_logits<<<edgeBlocks, 256>>>(src, dst, eattr, g1_we, g1_att,
                                         xl, xr, g_expl, den, E, Etot);
    gat_edge_aggr<<<edgeBlocks, 256>>>(src, dst, xl, g_expl, den, gout, E, Etot);
    gat_finalize<<<(ndTot + 255) / 256, 256>>>(gout, g1_bias, gin, ndTot);

    // ------------- fusion MLP -------------
    run_gemm(h1, HL, HL, fc1_w,
             gin, GD, GD, fc1_w + (size_t)HL * FH,
             fc1_b, nullptr, fc1buf, n, FH, /*transB=*/0, /*act=*/1);
    gemv_fc2<<<(n * 32 + 255) / 256, 256>>>(fc1buf, fc2_w, fc2_b,
                                            (float*)d_out, n);
}

// round 13
// speedup vs baseline: 1.5475x; 1.2437x over previous
#include <cuda_runtime.h>
#include <cuda_bf16.h>
#include <cstdint>
#include <cstdio>

// Problem constants
#define NN    10000
#define TT    60
#define FF    16
#define HL    256
#define G4H   1024     // 4*HL
#define GH    8
#define GC    64
#define GD    512
#define FH    512
#define EMAX  320000
#define ETOTMAX (EMAX + NN)

// ---------------- device scratch (no allocations allowed) ----------------
__device__ float g_h0[NN * HL];
__device__ float g_c0[NN * HL];
__device__ float g_h1[NN * HL];
__device__ float g_c1[NN * HL];
__device__ float g_xl[NN * GD];
__device__ float g_xr[NN * GD];
__device__ float g_gout[NN * GD];
__device__ float g_gin[NN * GD];
__device__ float g_den[NN * GH];
__device__ float g_expl[ETOTMAX * GH];
__device__ float g_fc1[NN * FH];
__device__ float g_partial[256];
__device__ float g_mean_buf[1];

// bf16 hi/lo splits
__device__ __nv_bfloat16 g_h0hi[NN * HL], g_h0lo[NN * HL];
__device__ __nv_bfloat16 g_h1hi[NN * HL], g_h1lo[NN * HL];
__device__ __nv_bfloat16 g_wih0hi[G4H * 32],  g_wih0lo[G4H * 32];   // K padded 16->32
__device__ __nv_bfloat16 g_whh0hi[G4H * HL],  g_whh0lo[G4H * HL];
__device__ __nv_bfloat16 g_wih1hi[G4H * HL],  g_wih1lo[G4H * HL];
__device__ __nv_bfloat16 g_whh1hi[G4H * HL],  g_whh1lo[G4H * HL];
__device__ float g_pb0[G4H], g_pb1[G4H];

// ---------------- helpers ---------------------------------------------------
__device__ __forceinline__ uint32_t pack_bf16_pair(float a, float b) {
    __nv_bfloat16 ba = __float2bfloat16(a);
    __nv_bfloat16 bb = __float2bfloat16(b);
    return ((uint32_t)__bfloat16_as_ushort(bb) << 16) | __bfloat16_as_ushort(ba);
}

__device__ __forceinline__ void mma_bf16(
    float& c0, float& c1, float& c2, float& c3,
    uint32_t a0, uint32_t a1, uint32_t a2, uint32_t a3,
    uint32_t b0, uint32_t b1)
{
    asm volatile(
        "mma.sync.aligned.m16n8k16.row.col.f32.bf16.bf16.f32 "
        "{%0,%1,%2,%3}, {%4,%5,%6,%7}, {%8,%9}, {%0,%1,%2,%3};"
        : "+f"(c0), "+f"(c1), "+f"(c2), "+f"(c3)
        : "r"(a0), "r"(a1), "r"(a2), "r"(a3), "r"(b0), "r"(b1));
}

// ---------------- weight split + gate permutation ---------------------------
// torch rows [4H x K]: row = q*256+u (q in i,f,g,o). New row (col of gates) =
// (u/32)*128 + q*32 + (u%32) so each 128-col tile has all gates for 32 units.
__global__ void split_perm_bf16(const float* __restrict__ w, int K, int Kp,
                                __nv_bfloat16* __restrict__ hi,
                                __nv_bfloat16* __restrict__ lo, int total)
{
    int idx = blockIdx.x * 256 + threadIdx.x;
    if (idx >= total) return;
    int row = idx / Kp, k = idx % Kp;
    int q = row >> 8, u = row & 255;
    int nr = ((u >> 5) << 7) + (q << 5) + (u & 31);
    float v = (k < K) ? w[(size_t)row * K + k] : 0.f;
    __nv_bfloat16 h = __float2bfloat16(v);
    hi[(size_t)nr * Kp + k] = h;
    lo[(size_t)nr * Kp + k] = __float2bfloat16(v - __bfloat162float(h));
}

__global__ void bias_perm(const float* __restrict__ bi, const float* __restrict__ bh,
                          float* __restrict__ pb)
{
    int row = blockIdx.x * 256 + threadIdx.x;
    if (row >= G4H) return;
    int q = row >> 8, u = row & 255;
    int nr = ((u >> 5) << 7) + (q << 5) + (u & 31);
    pb[nr] = bi[row] + bh[row];
}

// ---------------- fused LSTM step: dual-phase bf16 3-term MMA + cell -------
struct PhaseDesc {
    const float* Af;                 // fp32 A (or null)
    const __nv_bfloat16 *Ahi, *Alo;  // pre-split A (if Af null)
    int lda;                         // row stride in elements
    int Kp;                          // padded K (mult of 32)
    int Kreal;                       // valid cols for fp32 path
    const __nv_bfloat16 *Bhi, *Blo;  // [1024][Kp] row-major (permuted rows)
};

#define SROW 136                     // u32 stride for smem A/B rows (8*tig bank spread)
#define STEP_SMEM (128 * 132 * 4)    // 67584 B: staging dominates (GEMM bufs alias)

extern __shared__ uint32_t s_u32[];

__global__ __launch_bounds__(256) void lstm_step(
    PhaseDesc P0, PhaseDesc P1,
    const float* __restrict__ pbias,
    float* __restrict__ h, float* __restrict__ c,
    __nv_bfloat16* __restrict__ hhi, __nv_bfloat16* __restrict__ hlo,
    int Nr)
{
    uint32_t* sAh = s_u32;
    uint32_t* sAl = sAh + 16 * SROW;
    uint32_t* sBh = sAl + 16 * SROW;
    uint32_t* sBl = sBh + 16 * SROW;
    float*    sC  = (float*)s_u32;   // alias, used after compute

    const int tid  = threadIdx.x;
    const int lane = tid & 31;
    const int warp = tid >> 5;
    const int grp  = lane >> 2;      // 0..7
    const int tig  = lane & 3;       // 0..3
    const int wm   = (warp & 1) * 64;
    const int wn   = (warp >> 1) * 32;
    const int rowBase = blockIdx.y * 128;
    const int colBase = blockIdx.x * 128;

    float acc[4][4][4];
#pragma unroll
    for (int i = 0; i < 4; i++)
#pragma unroll
        for (int j = 0; j < 4; j++)
#pragma unroll
            for (int q = 0; q < 4; q++) acc[i][j][q] = 0.f;

    const int r    = tid >> 1;       // 0..127 (loader row)
    const int half = tid & 1;        // which 8 kpairs
    const int kp0  = half * 8;

#pragma unroll 1
    for (int phase = 0; phase < 2; phase++) {
        const PhaseDesc D = phase ? P1 : P0;
#pragma unroll 1
        for (int k0 = 0; k0 < D.Kp; k0 += 32) {
            // ---- stage A tile (hi/lo bf16x2, layout [kpair][m]) ----
            {
                int gr = rowBase + r;
                uint32_t ah[8], al[8];
                if (D.Af) {
#pragma unroll
                    for (int i = 0; i < 8; i++) {
                        int col = k0 + half * 16 + i * 2;
                        float2 v = make_float2(0.f, 0.f);
                        if (gr < Nr && col < D.Kreal)
                            v = *(const float2*)(D.Af + (size_t)gr * D.lda + col);
                        __nv_bfloat16 bx = __float2bfloat16(v.x);
                        __nv_bfloat16 by = __float2bfloat16(v.y);
                        ah[i] = ((uint32_t)__bfloat16_as_ushort(by) << 16) |
                                __bfloat16_as_ushort(bx);
                        al[i] = pack_bf16_pair(v.x - __bfloat162float(bx),
                                               v.y - __bfloat162float(by));
                    }
                } else if (gr < Nr) {
                    const uint32_t* ph = (const uint32_t*)(D.Ahi + (size_t)gr * D.lda + k0) + half * 8;
                    const uint32_t* pl = (const uint32_t*)(D.Alo + (size_t)gr * D.lda + k0) + half * 8;
                    uint4 v0 = *(const uint4*)ph;
                    uint4 v1 = *(const uint4*)(ph + 4);
                    ah[0] = v0.x; ah[1] = v0.y; ah[2] = v0.z; ah[3] = v0.w;
                    ah[4] = v1.x; ah[5] = v1.y; ah[6] = v1.z; ah[7] = v1.w;
                    uint4 w0 = *(const uint4*)pl;
                    uint4 w1 = *(const uint4*)(pl + 4);
                    al[0] = w0.x; al[1] = w0.y; al[2] = w0.z; al[3] = w0.w;
                    al[4] = w1.x; al[5] = w1.y; al[6] = w1.z; al[7] = w1.w;
                } else {
#pragma unroll
                    for (int i = 0; i < 8; i++) { ah[i] = 0u; al[i] = 0u; }
                }
#pragma unroll
                for (int i = 0; i < 8; i++) {
                    sAh[(kp0 + i) * SROW + r] = ah[i];
                    sAl[(kp0 + i) * SROW + r] = al[i];
                }
            }
            // ---- stage B tile ([kpair][n]) ----
            {
                int br = colBase + r;
                const uint32_t* ph = (const uint32_t*)(D.Bhi + (size_t)br * D.Kp + k0) + half * 8;
                const uint32_t* pl = (const uint32_t*)(D.Blo + (size_t)br * D.Kp + k0) + half * 8;
                uint4 v0 = *(const uint4*)ph;
                uint4 v1 = *(const uint4*)(ph + 4);
                uint4 w0 = *(const uint4*)pl;
                uint4 w1 = *(const uint4*)(pl + 4);
                uint32_t bh[8] = {v0.x, v0.y, v0.z, v0.w, v1.x, v1.y, v1.z, v1.w};
                uint32_t bl[8] = {w0.x, w0.y, w0.z, w0.w, w1.x, w1.y, w1.z, w1.w};
#pragma unroll
                for (int i = 0; i < 8; i++) {
                    sBh[(kp0 + i) * SROW + r] = bh[i];
                    sBl[(kp0 + i) * SROW + r] = bl[i];
                }
            }
            __syncthreads();

            // ---- compute: 2 x k16 halves, 3-term bf16 ----
#pragma unroll
            for (int kh = 0; kh < 2; kh++) {
                const int kb = kh * 8;
                uint32_t bh0[4], bh1[4], bl0[4], bl1[4];
#pragma unroll
                for (int nt = 0; nt < 4; nt++) {
                    int n0 = wn + nt * 8 + grp;
                    bh0[nt] = sBh[(kb + tig) * SROW + n0];
                    bh1[nt] = sBh[(kb + tig + 4) * SROW + n0];
                    bl0[nt] = sBl[(kb + tig) * SROW + n0];
                    bl1[nt] = sBl[(kb + tig + 4) * SROW + n0];
                }
#pragma unroll
                for (int mt = 0; mt < 4; mt++) {
                    int m0 = wm + mt * 16 + grp;
                    uint32_t ah0 = sAh[(kb + tig) * SROW + m0];
                    uint32_t ah1 = sAh[(kb + tig) * SROW + m0 + 8];
                    uint32_t ah2 = sAh[(kb + tig + 4) * SROW + m0];
                    uint32_t ah3 = sAh[(kb + tig + 4) * SROW + m0 + 8];
                    uint32_t al0 = sAl[(kb + tig) * SROW + m0];
                    uint32_t al1 = sAl[(kb + tig) * SROW + m0 + 8];
                    uint32_t al2 = sAl[(kb + tig + 4) * SROW + m0];
                    uint32_t al3 = sAl[(kb + tig + 4) * SROW + m0 + 8];
#pragma unroll
                    for (int nt = 0; nt < 4; nt++) {
                        float* cc = acc[mt][nt];
                        mma_bf16(cc[0], cc[1], cc[2], cc[3],
                                 ah0, ah1, ah2, ah3, bh0[nt], bh1[nt]);
                        mma_bf16(cc[0], cc[1], cc[2], cc[3],
                                 ah0, ah1, ah2, ah3, bl0[nt], bl1[nt]);
                        mma_bf16(cc[0], cc[1], cc[2], cc[3],
                                 al0, al1, al2, al3, bh0[nt], bh1[nt]);
                    }
                }
            }
            __syncthreads();
        }
    }

    // ---- stage gates tile to smem (alias of GEMM buffers) ----
#pragma unroll
    for (int mt = 0; mt < 4; mt++) {
        int rr = wm + mt * 16 + grp;
#pragma unroll
        for (int nt = 0; nt < 4; nt++) {
            int cc = wn + nt * 8 + 2 * tig;
            sC[rr * 132 + cc]           = acc[mt][nt][0];
            sC[rr * 132 + cc + 1]       = acc[mt][nt][1];
            sC[(rr + 8) * 132 + cc]     = acc[mt][nt][2];
            sC[(rr + 8) * 132 + cc + 1] = acc[mt][nt][3];
        }
    }
    __syncthreads();

    // ---- fused LSTM cell: this tile holds all 4 gates for 32 units ----
    const int v  = tid & 31;
    const int rg = tid >> 5;                 // warp -> 16-row slice
    const float b_i = pbias[colBase + v];
    const float b_f = pbias[colBase + 32 + v];
    const float b_g = pbias[colBase + 64 + v];
    const float b_o = pbias[colBase + 96 + v];
    const int u = blockIdx.x * 32 + v;
#pragma unroll 4
    for (int i = 0; i < 16; i++) {
        int rr = rg * 16 + i;
        int gr = rowBase + rr;
        if (gr >= Nr) continue;
        float gi = sC[rr * 132 + v]      + b_i;
        float gf = sC[rr * 132 + 32 + v] + b_f;
        float gg = sC[rr * 132 + 64 + v] + b_g;
        float go = sC[rr * 132 + 96 + v] + b_o;
        size_t off = (size_t)gr * HL + u;
        float cp = c[off];
        float si = 1.f / (1.f + __expf(-gi));
        float sf = 1.f / (1.f + __expf(-gf));
        float so = 1.f / (1.f + __expf(-go));
        float cn = sf * cp + si * tanhf(gg);
        float hn = so * tanhf(cn);
        c[off] = cn;
        h[off] = hn;
        __nv_bfloat16 hb = __float2bfloat16(hn);
        hhi[off] = hb;
        hlo[off] = __float2bfloat16(hn - __bfloat162float(hb));
    }
}

// ---------------- GEMM (SIMT fp32) for GAT/MLP -----------------------------
#define BM 128
#define BN 128
#define BK 8

__global__ __launch_bounds__(256) void gemm_dual(
    const float* __restrict__ A1, int lda1, int K1, const float* __restrict__ B1,
    const float* __restrict__ A2, int lda2, int K2, const float* __restrict__ B2,
    const float* __restrict__ bias1, const float* __restrict__ bias2,
    float* __restrict__ C, int Nr, int M, int transB, int act)
{
    __shared__ float As[BK][BM];
    __shared__ float Bs[BK][BN];

    const int tid = threadIdx.x;
    const int tx = tid & 15;
    const int ty = tid >> 4;
    const int rowBase = blockIdx.y * BM;
    const int colBase = blockIdx.x * BN;

    float acc[8][8];
#pragma unroll
    for (int i = 0; i < 8; i++)
#pragma unroll
        for (int j = 0; j < 8; j++) acc[i][j] = 0.f;

    for (int phase = 0; phase < 2; phase++) {
        const float* A = phase ? A2 : A1;
        const float* B = phase ? B2 : B1;
        const int K   = phase ? K2 : K1;
        const int lda = phase ? lda2 : lda1;
        for (int k0 = 0; k0 < K; k0 += BK) {
            {
                int rr = tid >> 1;
                int kq = (tid & 1) * 4;
                int gr = rowBase + rr;
                float4 vv = make_float4(0.f, 0.f, 0.f, 0.f);
                if (gr < Nr)
                    vv = *(const float4*)(A + (size_t)gr * lda + k0 + kq);
                As[kq + 0][rr] = vv.x; As[kq + 1][rr] = vv.y;
                As[kq + 2][rr] = vv.z; As[kq + 3][rr] = vv.w;
            }
            if (transB) {
                int rr = tid >> 1;
                int kq = (tid & 1) * 4;
                float4 vv = *(const float4*)(B + (size_t)(colBase + rr) * K + k0 + kq);
                Bs[kq + 0][rr] = vv.x; Bs[kq + 1][rr] = vv.y;
                Bs[kq + 2][rr] = vv.z; Bs[kq + 3][rr] = vv.w;
            } else {
                int kk = tid >> 5;
                int n4 = (tid & 31) * 4;
                float4 vv = *(const float4*)(B + (size_t)(k0 + kk) * M + colBase + n4);
                Bs[kk][n4 + 0] = vv.x; Bs[kk][n4 + 1] = vv.y;
                Bs[kk][n4 + 2] = vv.z; Bs[kk][n4 + 3] = vv.w;
            }
            __syncthreads();
#pragma unroll
            for (int k = 0; k < BK; k++) {
                float4 a0 = *(const float4*)&As[k][ty * 8];
                float4 a1 = *(const float4*)&As[k][ty * 8 + 4];
                float4 b0 = *(const float4*)&Bs[k][tx * 8];
                float4 b1 = *(const float4*)&Bs[k][tx * 8 + 4];
                float ra[8] = {a0.x, a0.y, a0.z, a0.w, a1.x, a1.y, a1.z, a1.w};
                float rb[8] = {b0.x, b0.y, b0.z, b0.w, b1.x, b1.y, b1.z, b1.w};
#pragma unroll
                for (int i = 0; i < 8; i++)
#pragma unroll
                    for (int j = 0; j < 8; j++)
                        acc[i][j] = fmaf(ra[i], rb[j], acc[i][j]);
            }
            __syncthreads();
        }
    }

#pragma unroll
    for (int i = 0; i < 8; i++) {
        int gr = rowBase + ty * 8 + i;
        if (gr >= Nr) continue;
#pragma unroll
        for (int j = 0; j < 8; j++) {
            int gc = colBase + tx * 8 + j;
            float vv = acc[i][j];
            if (bias1) vv += bias1[gc];
            if (bias2) vv += bias2[gc];
            if (act == 1) vv = fmaxf(vv, 0.f);
            C[(size_t)gr * M + gc] = vv;
        }
    }
}

// ---------------- edge_attr mean (deterministic 2-stage) -------------------
__global__ void reduce_mean1(const float* __restrict__ ea, int E)
{
    __shared__ float s[256];
    int tid = threadIdx.x;
    float acc = 0.f;
    for (int i = blockIdx.x * 256 + tid; i < E; i += 256 * 256) acc += ea[i];
    s[tid] = acc;
    __syncthreads();
    for (int off = 128; off > 0; off >>= 1) {
        if (tid < off) s[tid] += s[tid + off];
        __syncthreads();
    }
    if (tid == 0) g_partial[blockIdx.x] = s[0];
}

__global__ void reduce_mean2(int E)
{
    __shared__ float s[256];
    int tid = threadIdx.x;
    s[tid] = g_partial[tid];
    __syncthreads();
    for (int off = 128; off > 0; off >>= 1) {
        if (tid < off) s[tid] += s[tid + off];
        __syncthreads();
    }
    if (tid == 0) g_mean_buf[0] = s[0] / (float)E;
}

// ---------------- GAT edge pass 1: logits -> exp, accumulate denominator ---
__global__ void gat_edge_logits(
    const int* __restrict__ src, const int* __restrict__ dst,
    const float* __restrict__ ea,
    const float* __restrict__ we, const float* __restrict__ att,
    const float* __restrict__ xl, const float* __restrict__ xr,
    float* __restrict__ expl, float* __restrict__ den,
    int E, int Etot)
{
    int idx = blockIdx.x * blockDim.x + threadIdx.x;
    if (idx >= Etot * GH) return;
    int e = idx >> 3;
    int h = idx & 7;
    int s, d; float a;
    if (e < E) { s = src[e]; d = dst[e]; a = ea[e]; }
    else       { s = d = e - E;          a = g_mean_buf[0]; }

    const float4* pl = (const float4*)(xl + (size_t)s * GD + h * GC);
    const float4* pr = (const float4*)(xr + (size_t)d * GD + h * GC);
    const float4* pw = (const float4*)(we + h * GC);
    const float4* pa = (const float4*)(att + h * GC);

    float acc = 0.f;
#pragma unroll
    for (int c4 = 0; c4 < GC / 4; c4++) {
        float4 vl = pl[c4], vr = pr[c4], vw = pw[c4], va = pa[c4];
        float m;
        m = vl.x + vr.x + a * vw.x; m = m > 0.f ? m : 0.2f * m; acc += m * va.x;
        m = vl.y + vr.y + a * vw.y; m = m > 0.f ? m : 0.2f * m; acc += m * va.y;
        m = vl.z + vr.z + a * vw.z; m = m > 0.f ? m : 0.2f * m; acc += m * va.z;
        m = vl.w + vr.w + a * vw.w; m = m > 0.f ? m : 0.2f * m; acc += m * va.w;
    }
    float ex = __expf(acc);
    expl[idx] = ex;
    atomicAdd(&den[d * GH + h], ex);
}

// ---------------- GAT edge pass 2: weighted aggregation --------------------
__global__ void gat_edge_aggr(
    const int* __restrict__ src, const int* __restrict__ dst,
    const float* __restrict__ xl,
    const float* __restrict__ expl, const float* __restrict__ den,
    float* __restrict__ gout,
    int E, int Etot)
{
    int idx = blockIdx.x * blockDim.x + threadIdx.x;
    if (idx >= Etot * GH) return;
    int e = idx >> 3;
    int h = idx & 7;
    int s, d;
    if (e < E) { s = src[e]; d = dst[e]; }
    else       { s = d = e - E; }

    float alpha = expl[idx] / den[d * GH + h];
    const float4* pl = (const float4*)(xl + (size_t)s * GD + h * GC);
    float* po = gout + (size_t)d * GD + h * GC;
#pragma unroll
    for (int c4 = 0; c4 < GC / 4; c4++) {
        float4 vv = pl[c4];
        atomicAdd(&po[c4 * 4 + 0], vv.x * alpha);
        atomicAdd(&po[c4 * 4 + 1], vv.y * alpha);
        atomicAdd(&po[c4 * 4 + 2], vv.z * alpha);
        atomicAdd(&po[c4 * 4 + 3], vv.w * alpha);
    }
}

// ---------------- GAT finalize: +bias, ELU ---------------------------------
__global__ void gat_finalize(const float* __restrict__ gout,
                             const float* __restrict__ bias,
                             float* __restrict__ out, int total)
{
    int idx = blockIdx.x * blockDim.x + threadIdx.x;
    if (idx >= total) return;
    float vv = gout[idx] + bias[idx & (GD - 1)];
    out[idx] = vv > 0.f ? vv : expm1f(vv);
}

// ---------------- fc2 GEMV -------------------------------------------------
__global__ void gemv_fc2(const float* __restrict__ hbuf,
                         const float* __restrict__ w, const float* __restrict__ b,
                         float* __restrict__ out, int n)
{
    int gw = (blockIdx.x * blockDim.x + threadIdx.x) >> 5;
    int lane = threadIdx.x & 31;
    if (gw >= n) return;
    const float* row = hbuf + (size_t)gw * FH;
    float acc = 0.f;
#pragma unroll
    for (int k = lane; k < FH; k += 32) acc += row[k] * w[k];
#pragma unroll
    for (int off = 16; off > 0; off >>= 1) acc += __shfl_xor_sync(0xffffffffu, acc, off);
    if (lane == 0) out[gw] = acc + b[0];
}

// ---------------- host orchestration ---------------------------------------
static inline void run_gemm(const float* A1, int lda1, int K1, const float* B1,
                            const float* A2, int lda2, int K2, const float* B2,
                            const float* bias1, const float* bias2,
                            float* C, int Nr, int M, int transB, int act)
{
    dim3 grid((M + BN - 1) / BN, (Nr + BM - 1) / BM);
    gemm_dual<<<grid, 256>>>(A1, lda1, K1, B1, A2, lda2, K2, B2,
                             bias1, bias2, C, Nr, M, transB, act);
}

extern "C" void kernel_launch(void* const* d_in, const int* in_sizes, int n_in,
                              void* d_out, int out_size)
{
    const float* x_seq  = (const float*)d_in[0];
    const int*   eidx   = (const int*)  d_in[1];
    const float* eattr  = (const float*)d_in[2];
    const float* w_ih0  = (const float*)d_in[3];
    const float* w_hh0  = (const float*)d_in[4];
    const float* b_ih0  = (const float*)d_in[5];
    const float* b_hh0  = (const float*)d_in[6];
    const float* w_ih1  = (const float*)d_in[7];
    const float* w_hh1  = (const float*)d_in[8];
    const float* b_ih1  = (const float*)d_in[9];
    const float* b_hh1  = (const float*)d_in[10];
    const float* g0_wl  = (const float*)d_in[11];
    const float* g0_bl  = (const float*)d_in[12];
    const float* g0_wr  = (const float*)d_in[13];
    const float* g0_br  = (const float*)d_in[14];
    const float* g0_we  = (const float*)d_in[15];
    const float* g0_att = (const float*)d_in[16];
    const float* g0_bias= (const float*)d_in[17];
    const float* g1_wl  = (const float*)d_in[18];
    const float* g1_bl  = (const float*)d_in[19];
    const float* g1_wr  = (const float*)d_in[20];
    const float* g1_br  = (const float*)d_in[21];
    const float* g1_we  = (const float*)d_in[22];
    const float* g1_att = (const float*)d_in[23];
    const float* g1_bias= (const float*)d_in[24];
    const float* fc1_w  = (const float*)d_in[25];
    const float* fc1_b  = (const float*)d_in[26];
    const float* fc2_w  = (const float*)d_in[27];
    const float* fc2_b  = (const float*)d_in[28];

    const int n = in_sizes[0] / (TT * FF);
    const int E = in_sizes[2];
    const int Etot = E + n;
    const int* src = eidx;
    const int* dst = eidx + E;

    float *h0, *c0, *h1, *c1, *xl, *xr, *gout, *gin, *den, *fc1buf, *pb0, *pb1;
    __nv_bfloat16 *h0hi, *h0lo, *h1hi, *h1lo;
    __nv_bfloat16 *wih0hi, *wih0lo, *whh0hi, *whh0lo, *wih1hi, *wih1lo, *whh1hi, *whh1lo;
    cudaGetSymbolAddress((void**)&h0, g_h0);
    cudaGetSymbolAddress((void**)&c0, g_c0);
    cudaGetSymbolAddress((void**)&h1, g_h1);
    cudaGetSymbolAddress((void**)&c1, g_c1);
    cudaGetSymbolAddress((void**)&xl, g_xl);
    cudaGetSymbolAddress((void**)&xr, g_xr);
    cudaGetSymbolAddress((void**)&gout, g_gout);
    cudaGetSymbolAddress((void**)&gin, g_gin);
    cudaGetSymbolAddress((void**)&den, g_den);
    cudaGetSymbolAddress((void**)&fc1buf, g_fc1);
    cudaGetSymbolAddress((void**)&pb0, g_pb0);
    cudaGetSymbolAddress((void**)&pb1, g_pb1);
    cudaGetSymbolAddress((void**)&h0hi, g_h0hi);
    cudaGetSymbolAddress((void**)&h0lo, g_h0lo);
    cudaGetSymbolAddress((void**)&h1hi, g_h1hi);
    cudaGetSymbolAddress((void**)&h1lo, g_h1lo);
    cudaGetSymbolAddress((void**)&wih0hi, g_wih0hi);
    cudaGetSymbolAddress((void**)&wih0lo, g_wih0lo);
    cudaGetSymbolAddress((void**)&whh0hi, g_whh0hi);
    cudaGetSymbolAddress((void**)&whh0lo, g_whh0lo);
    cudaGetSymbolAddress((void**)&wih1hi, g_wih1hi);
    cudaGetSymbolAddress((void**)&wih1lo, g_wih1lo);
    cudaGetSymbolAddress((void**)&whh1hi, g_whh1hi);
    cudaGetSymbolAddress((void**)&whh1lo, g_whh1lo);

    static int smem_set = 0;
    if (!smem_set) {
        cudaFuncSetAttribute(lstm_step, cudaFuncAttributeMaxDynamicSharedMemorySize,
                             STEP_SMEM);
        smem_set = 1;
    }

    // init states (h splits are bf16 zero = 0x0000)
    cudaMemsetAsync(h0, 0, (size_t)n * HL * sizeof(float));
    cudaMemsetAsync(c0, 0, (size_t)n * HL * sizeof(float));
    cudaMemsetAsync(h1, 0, (size_t)n * HL * sizeof(float));
    cudaMemsetAsync(c1, 0, (size_t)n * HL * sizeof(float));
    cudaMemsetAsync(h0hi, 0, (size_t)n * HL * sizeof(__nv_bfloat16));
    cudaMemsetAsync(h0lo, 0, (size_t)n * HL * sizeof(__nv_bfloat16));
    cudaMemsetAsync(h1hi, 0, (size_t)n * HL * sizeof(__nv_bfloat16));
    cudaMemsetAsync(h1lo, 0, (size_t)n * HL * sizeof(__nv_bfloat16));

    // edge_attr mean (for self-loop fill)
    reduce_mean1<<<256, 256>>>(eattr, E);
    reduce_mean2<<<1, 256>>>(E);

    // split + permute LSTM weights to bf16 hi/lo
    split_perm_bf16<<<(G4H * 32 + 255) / 256, 256>>>(w_ih0, FF, 32, wih0hi, wih0lo, G4H * 32);
    split_perm_bf16<<<(G4H * HL + 255) / 256, 256>>>(w_hh0, HL, HL, whh0hi, whh0lo, G4H * HL);
    split_perm_bf16<<<(G4H * HL + 255) / 256, 256>>>(w_ih1, HL, HL, wih1hi, wih1lo, G4H * HL);
    split_perm_bf16<<<(G4H * HL + 255) / 256, 256>>>(w_hh1, HL, HL, whh1hi, whh1lo, G4H * HL);
    bias_perm<<<4, 256>>>(b_ih0, b_hh0, pb0);
    bias_perm<<<4, 256>>>(b_ih1, b_hh1, pb1);

    // ------------- LSTM: fused GEMM+cell per layer per step -------------
    dim3 lgrid(8, (n + 127) / 128);
    for (int t = 0; t < TT; t++) {
        PhaseDesc p00 = { x_seq + (size_t)t * FF, nullptr, nullptr, TT * FF, 32, FF,
                          wih0hi, wih0lo };
        PhaseDesc p01 = { nullptr, h0hi, h0lo, HL, HL, HL, whh0hi, whh0lo };
        lstm_step<<<lgrid, 256, STEP_SMEM>>>(p00, p01, pb0, h0, c0, h0hi, h0lo, n);

        PhaseDesc p10 = { nullptr, h0hi, h0lo, HL, HL, HL, wih1hi, wih1lo };
        PhaseDesc p11 = { nullptr, h1hi, h1lo, HL, HL, HL, whh1hi, whh1lo };
        lstm_step<<<lgrid, 256, STEP_SMEM>>>(p10, p11, pb1, h1, c1, h1hi, h1lo, n);
    }
    // node features = h1 (layer-1 hidden at last step)

    const int edgeThreads = Etot * GH;
    const int edgeBlocks  = (edgeThreads + 255) / 256;
    const int ndTot = n * GD;

    // ------------- GAT layer 0 (input: h1, K=256) -------------
    run_gemm(h1, HL, HL, g0_wl, nullptr, 0, 0, nullptr, g0_bl, nullptr,
             xl, n, GD, /*transB=*/0, 0);
    run_gemm(h1, HL, HL, g0_wr, nullptr, 0, 0, nullptr, g0_br, nullptr,
             xr, n, GD, 0, 0);
    cudaMemsetAsync(den, 0, (size_t)n * GH * sizeof(float));
    cudaMemsetAsync(gout, 0, (size_t)ndTot * sizeof(float));
    gat_edge_logits<<<edgeBlocks, 256>>>(src, dst, eattr, g0_we, g0_att,
                                         xl, xr, g_expl, den, E, Etot);
    gat_edge_aggr<<<edgeBlocks, 256>>>(src, dst, xl, g_expl, den, gout, E, Etot);
    gat_finalize<<<(ndTot + 255) / 256, 256>>>(gout, g0_bias, gin, ndTot);

    // ------------- GAT layer 1 (input: gin, K=512) -------------
    run_gemm(gin, GD, GD, g1_wl, nullptr, 0, 0, nullptr, g1_bl, nullptr,
             xl, n, GD, 0, 0);
    run_gemm(gin, GD, GD, g1_wr, nullptr, 0, 0, nullptr, g1_br, nullptr,
             xr, n, GD, 0, 0);
    cudaMemsetAsync(den, 0, (size_t)n * GH * sizeof(float));
    cudaMemsetAsync(gout, 0, (size_t)ndTot * sizeof(float));
    gat_edge_logits<<<edgeBlocks, 256>>>(src, dst, eattr, g1_we, g1_att,
                                         xl, xr, g_expl, den, E, Etot);
    gat_edge_aggr<<<edgeBlocks, 256>>>(src, dst, xl, g_expl, den, gout, E, Etot);
    gat_finalize<<<(ndTot + 255) / 256, 256>>>(gout, g1_bias, gin, ndTot);

    // ------------- fusion MLP -------------
    run_gemm(h1, HL, HL, fc1_w,
             gin, GD, GD, fc1_w + (size_t)HL * FH,
             fc1_b, nullptr, fc1buf, n, FH, /*transB=*/0, /*act=*/1);
    gemv_fc2<<<(n * 32 + 255) / 256, 256>>>(fc1buf, fc2_w, fc2_b,
                                            (float*)d_out, n);
}

// round 15
// speedup vs baseline: 1.5825x; 1.0226x over previous
#include <cuda_runtime.h>
#include <cuda_bf16.h>
#include <cstdint>
#include <cstdio>

// Problem constants
#define NN    10000
#define TT    60
#define FF    16
#define HL    256
#define G4H   1024     // 4*HL
#define GH    8
#define GC    64
#define GD    512
#define FH    512
#define EMAX  320000
#define ETOTMAX (EMAX + NN)

// ---------------- device scratch (no allocations allowed) ----------------
__device__ float g_h0[NN * HL];
__device__ float g_c0[NN * HL];
__device__ float g_h1[NN * HL];
__device__ float g_c1[NN * HL];
__device__ float g_xl[NN * GD];
__device__ float g_xr[NN * GD];
__device__ float g_gout[NN * GD];
__device__ float g_gin[NN * GD];
__device__ float g_den[NN * GH];
__device__ float g_expl[ETOTMAX * GH];
__device__ float g_fc1[NN * FH];
__device__ float g_partial[256];
__device__ float g_mean_buf[1];

// bf16 hi/lo splits
__device__ __nv_bfloat16 g_h0hi[NN * HL], g_h0lo[NN * HL];
__device__ __nv_bfloat16 g_h1hi[NN * HL], g_h1lo[NN * HL];
__device__ __nv_bfloat16 g_xhi[TT * NN * 32], g_xlo[TT * NN * 32];  // K padded 16->32
__device__ __nv_bfloat16 g_wih0hi[G4H * 32],  g_wih0lo[G4H * 32];
__device__ __nv_bfloat16 g_whh0hi[G4H * HL],  g_whh0lo[G4H * HL];
__device__ __nv_bfloat16 g_wih1hi[G4H * HL],  g_wih1lo[G4H * HL];
__device__ __nv_bfloat16 g_whh1hi[G4H * HL],  g_whh1lo[G4H * HL];
__device__ float g_pb0[G4H], g_pb1[G4H];

// ---------------- helpers ---------------------------------------------------
__device__ __forceinline__ void mma_bf16(
    float& c0, float& c1, float& c2, float& c3,
    uint32_t a0, uint32_t a1, uint32_t a2, uint32_t a3,
    uint32_t b0, uint32_t b1)
{
    asm volatile(
        "mma.sync.aligned.m16n8k16.row.col.f32.bf16.bf16.f32 "
        "{%0,%1,%2,%3}, {%4,%5,%6,%7}, {%8,%9}, {%0,%1,%2,%3};"
        : "+f"(c0), "+f"(c1), "+f"(c2), "+f"(c3)
        : "r"(a0), "r"(a1), "r"(a2), "r"(a3), "r"(b0), "r"(b1));
}

// ---------------- weight split + gate permutation ---------------------------
// torch rows [4H x K]: row = q*256+u (q in i,f,g,o). New row (col of gates) =
// (u/32)*128 + q*32 + (u%32) so each 128-col tile has all gates for 32 units.
__global__ void split_perm_bf16(const float* __restrict__ w, int K, int Kp,
                                __nv_bfloat16* __restrict__ hi,
                                __nv_bfloat16* __restrict__ lo, int total)
{
    int idx = blockIdx.x * 256 + threadIdx.x;
    if (idx >= total) return;
    int row = idx / Kp, k = idx % Kp;
    int q = row >> 8, u = row & 255;
    int nr = ((u >> 5) << 7) + (q << 5) + (u & 31);
    float v = (k < K) ? w[(size_t)row * K + k] : 0.f;
    __nv_bfloat16 h = __float2bfloat16(v);
    hi[(size_t)nr * Kp + k] = h;
    lo[(size_t)nr * Kp + k] = __float2bfloat16(v - __bfloat162float(h));
}

__global__ void bias_perm(const float* __restrict__ bi, const float* __restrict__ bh,
                          float* __restrict__ pb)
{
    int row = blockIdx.x * 256 + threadIdx.x;
    if (row >= G4H) return;
    int q = row >> 8, u = row & 255;
    int nr = ((u >> 5) << 7) + (q << 5) + (u & 31);
    pb[nr] = bi[row] + bh[row];
}

// ---------------- x pre-split: [N][T][F] -> hi/lo [T][N][32] ----------------
__global__ void split_x(const float* __restrict__ x,
                        __nv_bfloat16* __restrict__ xhi,
                        __nv_bfloat16* __restrict__ xlo, int n)
{
    int idx = blockIdx.x * 256 + threadIdx.x;
    if (idx >= TT * n * 32) return;
    int k  = idx & 31;
    int rn = (idx >> 5) % n;
    int t  = idx / (32 * n);
    float v = (k < FF) ? x[(size_t)rn * TT * FF + t * FF + k] : 0.f;
    __nv_bfloat16 h = __float2bfloat16(v);
    xhi[idx] = h;
    xlo[idx] = __float2bfloat16(v - __bfloat162float(h));
}

// ---------------- fused LSTM step: dual-phase bf16 3-term MMA + cell -------
// Double-buffered smem + register prefetch: globals for iter it+1 are loaded
// into registers before compute(it); STS happens after the trailing barrier.
// Compute path / smem layout / epilogue identical to the verified R13 kernel.
struct PhaseDesc {
    const __nv_bfloat16 *Ahi, *Alo;  // [rows][Kp] bf16 (pre-split)
    int Kp;                          // padded K (mult of 32), also row stride
    const __nv_bfloat16 *Bhi, *Blo;  // [1024][Kp] (permuted rows)
};

#define SROW 136                     // u32 stride for smem rows (bank spread)
#define STAGE_U32 (4 * 16 * SROW)    // 8704 u32 per stage (Ah,Al,Bh,Bl)
#define STEP_SMEM (2 * STAGE_U32 * 4)   // 69632 B (sC 67584 aliases)

extern __shared__ uint32_t s_u32[];

__global__ __launch_bounds__(256) void lstm_step(
    PhaseDesc P0, PhaseDesc P1,
    const float* __restrict__ pbias,
    float* __restrict__ h, float* __restrict__ c,
    __nv_bfloat16* __restrict__ hhi, __nv_bfloat16* __restrict__ hlo,
    int Nr)
{
    float* sC = (float*)s_u32;       // alias, used after compute

    const int tid  = threadIdx.x;
    const int lane = tid & 31;
    const int warp = tid >> 5;
    const int grp  = lane >> 2;      // 0..7
    const int tig  = lane & 3;       // 0..3
    const int wm   = (warp & 1) * 64;
    const int wn   = (warp >> 1) * 32;
    const int rowBase = blockIdx.y * 128;
    const int colBase = blockIdx.x * 128;

    const int n0iters = P0.Kp >> 5;
    const int niters  = n0iters + (P1.Kp >> 5);

    // loader mapping (verbatim R13): thread stages row r, 8 kpairs (half)
    const int r    = tid >> 1;       // 0..127
    const int half = tid & 1;
    const int kp0  = half * 8;
    const int gr   = rowBase + r;
    const bool aval = gr < Nr;
    const int br   = colBase + r;

    float acc[4][4][4];
#pragma unroll
    for (int i = 0; i < 4; i++)
#pragma unroll
        for (int j = 0; j < 4; j++)
#pragma unroll
            for (int q = 0; q < 4; q++) acc[i][j][q] = 0.f;

    // prefetch registers
    uint4 Rah0, Rah1, Ral0, Ral1, Rbh0, Rbh1, Rbl0, Rbl1;

    auto loadG = [&](int it) {
        const bool ph = it >= n0iters;
        const __nv_bfloat16* Ahi = ph ? P1.Ahi : P0.Ahi;
        const __nv_bfloat16* Alo = ph ? P1.Alo : P0.Alo;
        const __nv_bfloat16* Bhi = ph ? P1.Bhi : P0.Bhi;
        const __nv_bfloat16* Blo = ph ? P1.Blo : P0.Blo;
        const int Kp = ph ? P1.Kp : P0.Kp;
        const int k0 = (ph ? it - n0iters : it) << 5;
        if (aval) {
            const uint32_t* p = (const uint32_t*)(Ahi + (size_t)gr * Kp + k0) + half * 8;
            Rah0 = *(const uint4*)p;
            Rah1 = *(const uint4*)(p + 4);
            p = (const uint32_t*)(Alo + (size_t)gr * Kp + k0) + half * 8;
            Ral0 = *(const uint4*)p;
            Ral1 = *(const uint4*)(p + 4);
        } else {
            Rah0 = Rah1 = Ral0 = Ral1 = make_uint4(0u, 0u, 0u, 0u);
        }
        const uint32_t* q = (const uint32_t*)(Bhi + (size_t)br * Kp + k0) + half * 8;
        Rbh0 = *(const uint4*)q;
        Rbh1 = *(const uint4*)(q + 4);
        q = (const uint32_t*)(Blo + (size_t)br * Kp + k0) + half * 8;
        Rbl0 = *(const uint4*)q;
        Rbl1 = *(const uint4*)(q + 4);
    };

    auto stoS = [&](int it) {
        uint32_t* st  = s_u32 + (it & 1) * STAGE_U32;
        uint32_t* sAh = st;
        uint32_t* sAl = st + 16 * SROW;
        uint32_t* sBh = st + 32 * SROW;
        uint32_t* sBl = st + 48 * SROW;
        uint32_t ah[8] = {Rah0.x, Rah0.y, Rah0.z, Rah0.w, Rah1.x, Rah1.y, Rah1.z, Rah1.w};
        uint32_t al[8] = {Ral0.x, Ral0.y, Ral0.z, Ral0.w, Ral1.x, Ral1.y, Ral1.z, Ral1.w};
        uint32_t bh[8] = {Rbh0.x, Rbh0.y, Rbh0.z, Rbh0.w, Rbh1.x, Rbh1.y, Rbh1.z, Rbh1.w};
        uint32_t bl[8] = {Rbl0.x, Rbl0.y, Rbl0.z, Rbl0.w, Rbl1.x, Rbl1.y, Rbl1.z, Rbl1.w};
#pragma unroll
        for (int i = 0; i < 8; i++) {
            sAh[(kp0 + i) * SROW + r] = ah[i];
            sAl[(kp0 + i) * SROW + r] = al[i];
            sBh[(kp0 + i) * SROW + r] = bh[i];
            sBl[(kp0 + i) * SROW + r] = bl[i];
        }
    };

    loadG(0);
    stoS(0);

#pragma unroll 1
    for (int it = 0; it < niters; it++) {
        if (it + 1 < niters) loadG(it + 1);   // LDGs in flight over compute
        __syncthreads();                       // stage it visible

        const uint32_t* st  = s_u32 + (it & 1) * STAGE_U32;
        const uint32_t* sAh = st;
        const uint32_t* sAl = st + 16 * SROW;
        const uint32_t* sBh = st + 32 * SROW;
        const uint32_t* sBl = st + 48 * SROW;

        // ---- compute: 2 x k16 halves, 3-term bf16 (verbatim R13) ----
#pragma unroll
        for (int kh = 0; kh < 2; kh++) {
            const int kb = kh * 8;
            uint32_t bh0[4], bh1[4], bl0[4], bl1[4];
#pragma unroll
            for (int nt = 0; nt < 4; nt++) {
                int n0 = wn + nt * 8 + grp;
                bh0[nt] = sBh[(kb + tig) * SROW + n0];
                bh1[nt] = sBh[(kb + tig + 4) * SROW + n0];
                bl0[nt] = sBl[(kb + tig) * SROW + n0];
                bl1[nt] = sBl[(kb + tig + 4) * SROW + n0];
            }
#pragma unroll
            for (int mt = 0; mt < 4; mt++) {
                int m0 = wm + mt * 16 + grp;
                uint32_t ah0 = sAh[(kb + tig) * SROW + m0];
                uint32_t ah1 = sAh[(kb + tig) * SROW + m0 + 8];
                uint32_t ah2 = sAh[(kb + tig + 4) * SROW + m0];
                uint32_t ah3 = sAh[(kb + tig + 4) * SROW + m0 + 8];
                uint32_t al0 = sAl[(kb + tig) * SROW + m0];
                uint32_t al1 = sAl[(kb + tig) * SROW + m0 + 8];
                uint32_t al2 = sAl[(kb + tig + 4) * SROW + m0];
                uint32_t al3 = sAl[(kb + tig + 4) * SROW + m0 + 8];
#pragma unroll
                for (int nt = 0; nt < 4; nt++) {
                    float* cc = acc[mt][nt];
                    mma_bf16(cc[0], cc[1], cc[2], cc[3],
                             ah0, ah1, ah2, ah3, bh0[nt], bh1[nt]);
                    mma_bf16(cc[0], cc[1], cc[2], cc[3],
                             ah0, ah1, ah2, ah3, bl0[nt], bl1[nt]);
                    mma_bf16(cc[0], cc[1], cc[2], cc[3],
                             al0, al1, al2, al3, bh0[nt], bh1[nt]);
                }
            }
        }
        __syncthreads();                       // buf (it+1)&1 readers done
        if (it + 1 < niters) stoS(it + 1);
    }

    // ---- stage gates tile to smem (aliases staging buffers) ----
#pragma unroll
    for (int mt = 0; mt < 4; mt++) {
        int rr = wm + mt * 16 + grp;
#pragma unroll
        for (int nt = 0; nt < 4; nt++) {
            int cc = wn + nt * 8 + 2 * tig;
            sC[rr * 132 + cc]           = acc[mt][nt][0];
            sC[rr * 132 + cc + 1]       = acc[mt][nt][1];
            sC[(rr + 8) * 132 + cc]     = acc[mt][nt][2];
            sC[(rr + 8) * 132 + cc + 1] = acc[mt][nt][3];
        }
    }
    __syncthreads();

    // ---- fused LSTM cell: this tile holds all 4 gates for 32 units ----
    const int v  = tid & 31;
    const int rg = tid >> 5;
    const float b_i = pbias[colBase + v];
    const float b_f = pbias[colBase + 32 + v];
    const float b_g = pbias[colBase + 64 + v];
    const float b_o = pbias[colBase + 96 + v];
    const int u = blockIdx.x * 32 + v;
#pragma unroll 4
    for (int i = 0; i < 16; i++) {
        int rr = rg * 16 + i;
        int grr = rowBase + rr;
        if (grr >= Nr) continue;
        float gi = sC[rr * 132 + v]      + b_i;
        float gf = sC[rr * 132 + 32 + v] + b_f;
        float gg = sC[rr * 132 + 64 + v] + b_g;
        float go = sC[rr * 132 + 96 + v] + b_o;
        size_t off = (size_t)grr * HL + u;
        float cp = c[off];
        float si = 1.f / (1.f + __expf(-gi));
        float sf = 1.f / (1.f + __expf(-gf));
        float so = 1.f / (1.f + __expf(-go));
        float cn = sf * cp + si * tanhf(gg);
        float hn = so * tanhf(cn);
        c[off] = cn;
        h[off] = hn;
        __nv_bfloat16 hb = __float2bfloat16(hn);
        hhi[off] = hb;
        hlo[off] = __float2bfloat16(hn - __bfloat162float(hb));
    }
}

// ---------------- GEMM (SIMT fp32) for GAT/MLP -----------------------------
#define BM 128
#define BN 128
#define BK 8

__global__ __launch_bounds__(256) void gemm_dual(
    const float* __restrict__ A1, int lda1, int K1, const float* __restrict__ B1,
    const float* __restrict__ A2, int lda2, int K2, const float* __restrict__ B2,
    const float* __restrict__ bias1, const float* __restrict__ bias2,
    float* __restrict__ C, int Nr, int M, int transB, int act)
{
    __shared__ float As[BK][BM];
    __shared__ float Bs[BK][BN];

    const int tid = threadIdx.x;
    const int tx = tid & 15;
    const int ty = tid >> 4;
    const int rowBase = blockIdx.y * BM;
    const int colBase = blockIdx.x * BN;

    float acc[8][8];
#pragma unroll
    for (int i = 0; i < 8; i++)
#pragma unroll
        for (int j = 0; j < 8; j++) acc[i][j] = 0.f;

    for (int phase = 0; phase < 2; phase++) {
        const float* A = phase ? A2 : A1;
        const float* B = phase ? B2 : B1;
        const int K   = phase ? K2 : K1;
        const int lda = phase ? lda2 : lda1;
        for (int k0 = 0; k0 < K; k0 += BK) {
            {
                int rr = tid >> 1;
                int kq = (tid & 1) * 4;
                int gr = rowBase + rr;
                float4 vv = make_float4(0.f, 0.f, 0.f, 0.f);
                if (gr < Nr)
                    vv = *(const float4*)(A + (size_t)gr * lda + k0 + kq);
                As[kq + 0][rr] = vv.x; As[kq + 1][rr] = vv.y;
                As[kq + 2][rr] = vv.z; As[kq + 3][rr] = vv.w;
            }
            if (transB) {
                int rr = tid >> 1;
                int kq = (tid & 1) * 4;
                float4 vv = *(const float4*)(B + (size_t)(colBase + rr) * K + k0 + kq);
                Bs[kq + 0][rr] = vv.x; Bs[kq + 1][rr] = vv.y;
                Bs[kq + 2][rr] = vv.z; Bs[kq + 3][rr] = vv.w;
            } else {
                int kk = tid >> 5;
                int n4 = (tid & 31) * 4;
                float4 vv = *(const float4*)(B + (size_t)(k0 + kk) * M + colBase + n4);
                Bs[kk][n4 + 0] = vv.x; Bs[kk][n4 + 1] = vv.y;
                Bs[kk][n4 + 2] = vv.z; Bs[kk][n4 + 3] = vv.w;
            }
            __syncthreads();
#pragma unroll
            for (int k = 0; k < BK; k++) {
                float4 a0 = *(const float4*)&As[k][ty * 8];
                float4 a1 = *(const float4*)&As[k][ty * 8 + 4];
                float4 b0 = *(const float4*)&Bs[k][tx * 8];
                float4 b1 = *(const float4*)&Bs[k][tx * 8 + 4];
                float ra[8] = {a0.x, a0.y, a0.z, a0.w, a1.x, a1.y, a1.z, a1.w};
                float rb[8] = {b0.x, b0.y, b0.z, b0.w, b1.x, b1.y, b1.z, b1.w};
#pragma unroll
                for (int i = 0; i < 8; i++)
#pragma unroll
                    for (int j = 0; j < 8; j++)
                        acc[i][j] = fmaf(ra[i], rb[j], acc[i][j]);
            }
            __syncthreads();
        }
    }

#pragma unroll
    for (int i = 0; i < 8; i++) {
        int gr = rowBase + ty * 8 + i;
        if (gr >= Nr) continue;
#pragma unroll
        for (int j = 0; j < 8; j++) {
            int gc = colBase + tx * 8 + j;
            float vv = acc[i][j];
            if (bias1) vv += bias1[gc];
            if (bias2) vv += bias2[gc];
            if (act == 1) vv = fmaxf(vv, 0.f);
            C[(size_t)gr * M + gc] = vv;
        }
    }
}

// ---------------- edge_attr mean (deterministic 2-stage) -------------------
__global__ void reduce_mean1(const float* __restrict__ ea, int E)
{
    __shared__ float s[256];
    int tid = threadIdx.x;
    float acc = 0.f;
    for (int i = blockIdx.x * 256 + tid; i < E; i += 256 * 256) acc += ea[i];
    s[tid] = acc;
    __syncthreads();
    for (int off = 128; off > 0; off >>= 1) {
        if (tid < off) s[tid] += s[tid + off];
        __syncthreads();
    }
    if (tid == 0) g_partial[blockIdx.x] = s[0];
}

__global__ void reduce_mean2(int E)
{
    __shared__ float s[256];
    int tid = threadIdx.x;
    s[tid] = g_partial[tid];
    __syncthreads();
    for (int off = 128; off > 0; off >>= 1) {
        if (tid < off) s[tid] += s[tid + off];
        __syncthreads();
    }
    if (tid == 0) g_mean_buf[0] = s[0] / (float)E;
}

// ---------------- GAT edge pass 1: logits -> exp, accumulate denominator ---
__global__ void gat_edge_logits(
    const int* __restrict__ src, const int* __restrict__ dst,
    const float* __restrict__ ea,
    const float* __restrict__ we, const float* __restrict__ att,
    const float* __restrict__ xl, const float* __restrict__ xr,
    float* __restrict__ expl, float* __restrict__ den,
    int E, int Etot)
{
    int idx = blockIdx.x * blockDim.x + threadIdx.x;
    if (idx >= Etot * GH) return;
    int e = idx >> 3;
    int h = idx & 7;
    int s, d; float a;
    if (e < E) { s = src[e]; d = dst[e]; a = ea[e]; }
    else       { s = d = e - E;          a = g_mean_buf[0]; }

    const float4* pl = (const float4*)(xl + (size_t)s * GD + h * GC);
    const float4* pr = (const float4*)(xr + (size_t)d * GD + h * GC);
    const float4* pw = (const float4*)(we + h * GC);
    const float4* pa = (const float4*)(att + h * GC);

    float acc = 0.f;
#pragma unroll
    for (int c4 = 0; c4 < GC / 4; c4++) {
        float4 vl = pl[c4], vr = pr[c4], vw = pw[c4], va = pa[c4];
        float m;
        m = vl.x + vr.x + a * vw.x; m = m > 0.f ? m : 0.2f * m; acc += m * va.x;
        m = vl.y + vr.y + a * vw.y; m = m > 0.f ? m : 0.2f * m; acc += m * va.y;
        m = vl.z + vr.z + a * vw.z; m = m > 0.f ? m : 0.2f * m; acc += m * va.z;
        m = vl.w + vr.w + a * vw.w; m = m > 0.f ? m : 0.2f * m; acc += m * va.w;
    }
    float ex = __expf(acc);
    expl[idx] = ex;
    atomicAdd(&den[d * GH + h], ex);
}

// ---------------- GAT edge pass 2: weighted aggregation --------------------
__global__ void gat_edge_aggr(
    const int* __restrict__ src, const int* __restrict__ dst,
    const float* __restrict__ xl,
    const float* __restrict__ expl, const float* __restrict__ den,
    float* __restrict__ gout,
    int E, int Etot)
{
    int idx = blockIdx.x * blockDim.x + threadIdx.x;
    if (idx >= Etot * GH) return;
    int e = idx >> 3;
    int h = idx & 7;
    int s, d;
    if (e < E) { s = src[e]; d = dst[e]; }
    else       { s = d = e - E; }

    float alpha = expl[idx] / den[d * GH + h];
    const float4* pl = (const float4*)(xl + (size_t)s * GD + h * GC);
    float* po = gout + (size_t)d * GD + h * GC;
#pragma unroll
    for (int c4 = 0; c4 < GC / 4; c4++) {
        float4 vv = pl[c4];
        atomicAdd(&po[c4 * 4 + 0], vv.x * alpha);
        atomicAdd(&po[c4 * 4 + 1], vv.y * alpha);
        atomicAdd(&po[c4 * 4 + 2], vv.z * alpha);
        atomicAdd(&po[c4 * 4 + 3], vv.w * alpha);
    }
}

// ---------------- GAT finalize: +bias, ELU ---------------------------------
__global__ void gat_finalize(const float* __restrict__ gout,
                             const float* __restrict__ bias,
                             float* __restrict__ out, int total)
{
    int idx = blockIdx.x * blockDim.x + threadIdx.x;
    if (idx >= total) return;
    float vv = gout[idx] + bias[idx & (GD - 1)];
    out[idx] = vv > 0.f ? vv : expm1f(vv);
}

// ---------------- fc2 GEMV -------------------------------------------------
__global__ void gemv_fc2(const float* __restrict__ hbuf,
                         const float* __restrict__ w, const float* __restrict__ b,
                         float* __restrict__ out, int n)
{
    int gw = (blockIdx.x * blockDim.x + threadIdx.x) >> 5;
    int lane = threadIdx.x & 31;
    if (gw >= n) return;
    const float* row = hbuf + (size_t)gw * FH;
    float acc = 0.f;
#pragma unroll
    for (int k = lane; k < FH; k += 32) acc += row[k] * w[k];
#pragma unroll
    for (int off = 16; off > 0; off >>= 1) acc += __shfl_xor_sync(0xffffffffu, acc, off);
    if (lane == 0) out[gw] = acc + b[0];
}

// ---------------- host orchestration ---------------------------------------
static inline void run_gemm(const float* A1, int lda1, int K1, const float* B1,
                            const float* A2, int lda2, int K2, const float* B2,
                            const float* bias1, const float* bias2,
                            float* C, int Nr, int M, int transB, int act)
{
    dim3 grid((M + BN - 1) / BN, (Nr + BM - 1) / BM);
    gemm_dual<<<grid, 256>>>(A1, lda1, K1, B1, A2, lda2, K2, B2,
                             bias1, bias2, C, Nr, M, transB, act);
}

extern "C" void kernel_launch(void* const* d_in, const int* in_sizes, int n_in,
                              void* d_out, int out_size)
{
    const float* x_seq  = (const float*)d_in[0];
    const int*   eidx   = (const int*)  d_in[1];
    const float* eattr  = (const float*)d_in[2];
    const float* w_ih0  = (const float*)d_in[3];
    const float* w_hh0  = (const float*)d_in[4];
    const float* b_ih0  = (const float*)d_in[5];
    const float* b_hh0  = (const float*)d_in[6];
    const float* w_ih1  = (const float*)d_in[7];
    const float* w_hh1  = (const float*)d_in[8];
    const float* b_ih1  = (const float*)d_in[9];
    const float* b_hh1  = (const float*)d_in[10];
    const float* g0_wl  = (const float*)d_in[11];
    const float* g0_bl  = (const float*)d_in[12];
    const float* g0_wr  = (const float*)d_in[13];
    const float* g0_br  = (const float*)d_in[14];
    const float* g0_we  = (const float*)d_in[15];
    const float* g0_att = (const float*)d_in[16];
    const float* g0_bias= (const float*)d_in[17];
    const float* g1_wl  = (const float*)d_in[18];
    const float* g1_bl  = (const float*)d_in[19];
    const float* g1_wr  = (const float*)d_in[20];
    const float* g1_br  = (const float*)d_in[21];
    const float* g1_we  = (const float*)d_in[22];
    const float* g1_att = (const float*)d_in[23];
    const float* g1_bias= (const float*)d_in[24];
    const float* fc1_w  = (const float*)d_in[25];
    const float* fc1_b  = (const float*)d_in[26];
    const float* fc2_w  = (const float*)d_in[27];
    const float* fc2_b  = (const float*)d_in[28];

    const int n = in_sizes[0] / (TT * FF);
    const int E = in_sizes[2];
    const int Etot = E + n;
    const int* src = eidx;
    const int* dst = eidx + E;

    float *h0, *c0, *h1, *c1, *xl, *xr, *gout, *gin, *den, *fc1buf, *pb0, *pb1;
    __nv_bfloat16 *h0hi, *h0lo, *h1hi, *h1lo, *xhi, *xlo;
    __nv_bfloat16 *wih0hi, *wih0lo, *whh0hi, *whh0lo, *wih1hi, *wih1lo, *whh1hi, *whh1lo;
    cudaGetSymbolAddress((void**)&h0, g_h0);
    cudaGetSymbolAddress((void**)&c0, g_c0);
    cudaGetSymbolAddress((void**)&h1, g_h1);
    cudaGetSymbolAddress((void**)&c1, g_c1);
    cudaGetSymbolAddress((void**)&xl, g_xl);
    cudaGetSymbolAddress((void**)&xr, g_xr);
    cudaGetSymbolAddress((void**)&gout, g_gout);
    cudaGetSymbolAddress((void**)&gin, g_gin);
    cudaGetSymbolAddress((void**)&den, g_den);
    cudaGetSymbolAddress((void**)&fc1buf, g_fc1);
    cudaGetSymbolAddress((void**)&pb0, g_pb0);
    cudaGetSymbolAddress((void**)&pb1, g_pb1);
    cudaGetSymbolAddress((void**)&h0hi, g_h0hi);
    cudaGetSymbolAddress((void**)&h0lo, g_h0lo);
    cudaGetSymbolAddress((void**)&h1hi, g_h1hi);
    cudaGetSymbolAddress((void**)&h1lo, g_h1lo);
    cudaGetSymbolAddress((void**)&xhi, g_xhi);
    cudaGetSymbolAddress((void**)&xlo, g_xlo);
    cudaGetSymbolAddress((void**)&wih0hi, g_wih0hi);
    cudaGetSymbolAddress((void**)&wih0lo, g_wih0lo);
    cudaGetSymbolAddress((void**)&whh0hi, g_whh0hi);
    cudaGetSymbolAddress((void**)&whh0lo, g_whh0lo);
    cudaGetSymbolAddress((void**)&wih1hi, g_wih1hi);
    cudaGetSymbolAddress((void**)&wih1lo, g_wih1lo);
    cudaGetSymbolAddress((void**)&whh1hi, g_whh1hi);
    cudaGetSymbolAddress((void**)&whh1lo, g_whh1lo);

    static int smem_set = 0;
    if (!smem_set) {
        cudaFuncSetAttribute(lstm_step, cudaFuncAttributeMaxDynamicSharedMemorySize,
                             STEP_SMEM);
        smem_set = 1;
    }

    // init states (h splits are bf16 zero = 0x0000)
    cudaMemsetAsync(h0, 0, (size_t)n * HL * sizeof(float));
    cudaMemsetAsync(c0, 0, (size_t)n * HL * sizeof(float));
    cudaMemsetAsync(h1, 0, (size_t)n * HL * sizeof(float));
    cudaMemsetAsync(c1, 0, (size_t)n * HL * sizeof(float));
    cudaMemsetAsync(h0hi, 0, (size_t)n * HL * sizeof(__nv_bfloat16));
    cudaMemsetAsync(h0lo, 0, (size_t)n * HL * sizeof(__nv_bfloat16));
    cudaMemsetAsync(h1hi, 0, (size_t)n * HL * sizeof(__nv_bfloat16));
    cudaMemsetAsync(h1lo, 0, (size_t)n * HL * sizeof(__nv_bfloat16));

    // edge_attr mean (for self-loop fill)
    reduce_mean1<<<256, 256>>>(eattr, E);
    reduce_mean2<<<1, 256>>>(E);

    // split + permute LSTM weights to bf16 hi/lo; pre-split x for all t
    split_perm_bf16<<<(G4H * 32 + 255) / 256, 256>>>(w_ih0, FF, 32, wih0hi, wih0lo, G4H * 32);
    split_perm_bf16<<<(G4H * HL + 255) / 256, 256>>>(w_hh0, HL, HL, whh0hi, whh0lo, G4H * HL);
    split_perm_bf16<<<(G4H * HL + 255) / 256, 256>>>(w_ih1, HL, HL, wih1hi, wih1lo, G4H * HL);
    split_perm_bf16<<<(G4H * HL + 255) / 256, 256>>>(w_hh1, HL, HL, whh1hi, whh1lo, G4H * HL);
    bias_perm<<<4, 256>>>(b_ih0, b_hh0, pb0);
    bias_perm<<<4, 256>>>(b_ih1, b_hh1, pb1);
    split_x<<<(TT * n * 32 + 255) / 256, 256>>>(x_seq, xhi, xlo, n);

    // ------------- LSTM: fused GEMM+cell per layer per step -------------
    dim3 lgrid(8, (n + 127) / 128);
    for (int t = 0; t < TT; t++) {
        PhaseDesc p00 = { xhi + (size_t)t * n * 32, xlo + (size_t)t * n * 32, 32,
                          wih0hi, wih0lo };
        PhaseDesc p01 = { h0hi, h0lo, HL, whh0hi, whh0lo };
        lstm_step<<<lgrid, 256, STEP_SMEM>>>(p00, p01, pb0, h0, c0, h0hi, h0lo, n);

        PhaseDesc p10 = { h0hi, h0lo, HL, wih1hi, wih1lo };
        PhaseDesc p11 = { h1hi, h1lo, HL, whh1hi, whh1lo };
        lstm_step<<<lgrid, 256, STEP_SMEM>>>(p10, p11, pb1, h1, c1, h1hi, h1lo, n);
    }
    // node features = h1 (layer-1 hidden at last step)

    const int edgeThreads = Etot * GH;
    const int edgeBlocks  = (edgeThreads + 255) / 256;
    const int ndTot = n * GD;

    // ------------- GAT layer 0 (input: h1, K=256) -------------
    run_gemm(h1, HL, HL, g0_wl, nullptr, 0, 0, nullptr, g0_bl, nullptr,
             xl, n, GD, /*transB=*/0, 0);
    run_gemm(h1, HL, HL, g0_wr, nullptr, 0, 0, nullptr, g0_br, nullptr,
             xr, n, GD, 0, 0);
    cudaMemsetAsync(den, 0, (size_t)n * GH * sizeof(float));
    cudaMemsetAsync(gout, 0, (size_t)ndTot * sizeof(float));
    gat_edge_logits<<<edgeBlocks, 256>>>(src, dst, eattr, g0_we, g0_att,
                                         xl, xr, g_expl, den, E, Etot);
    gat_edge_aggr<<<edgeBlocks, 256>>>(src, dst, xl, g_expl, den, gout, E, Etot);
    gat_finalize<<<(ndTot + 255) / 256, 256>>>(gout, g0_bias, gin, ndTot);

    // ------------- GAT layer 1 (input: gin, K=512) -------------
    run_gemm(gin, GD, GD, g1_wl, nullptr, 0, 0, nullptr, g1_bl, nullptr,
             xl, n, GD, 0, 0);
    run_gemm(gin, GD, GD, g1_wr, nullptr, 0, 0, nullptr, g1_br, nullptr,
             xr, n, GD, 0, 0);
    cudaMemsetAsync(den, 0, (size_t)n * GH * sizeof(float));
    cudaMemsetAsync(gout, 0, (size_t)ndTot * sizeof(float));
    gat_edge_logits<<<edgeBlocks, 256>>>(src, dst, eattr, g1_we, g1_att,
                                         xl, xr, g_expl, den, E, Etot);
    gat_edge_aggr<<<edgeBlocks, 256>>>(src, dst, xl, g_expl, den, gout, E, Etot);
    gat_finalize<<<(ndTot + 255) / 256, 256>>>(gout, g1_bias, gin, ndTot);

    // ------------- fusion MLP -------------
    run_gemm(h1, HL, HL, fc1_w,
             gin, GD, GD, fc1_w + (size_t)HL * FH,
             fc1_b, nullptr, fc1buf, n, FH, /*transB=*/0, /*act=*/1);
    gemv_fc2<<<(n * 32 + 255) / 256, 256>>>(fc1buf, fc2_w, fc2_b,
                                            (float*)d_out, n);
}

// round 17
// speedup vs baseline: 2.5061x; 1.5837x over previous
#include <cuda_runtime.h>
#include <cuda_bf16.h>
#include <cuda_fp16.h>
#include <cstdint>
#include <cstdio>

// Problem constants
#define NN    10000
#define TT    60
#define FF    16
#define HL    256
#define G4H   1024     // 4*HL
#define GH    8
#define GC    64
#define GD    512
#define FH    512
#define EMAX  320000
#define ETOTMAX (EMAX + NN)

// ---------------- device scratch (no allocations allowed) ----------------
__device__ float g_c0[NN * HL];
__device__ float g_h1[NN * HL];
__device__ float g_c1[NN * HL];
__device__ float g_xl[NN * GD];
__device__ float g_xr[NN * GD];
__device__ float g_gout[NN * GD];
__device__ float g_gin[NN * GD];
__device__ float g_den[NN * GH];
__device__ float g_expl[ETOTMAX * GH];
__device__ float g_fc1[NN * FH];
__device__ float g_partial[256];
__device__ float g_mean_buf[1];

// fp16 state (double-buffered for wavefront) + inputs + weights (hi/lo)
__device__ __half g_h016a[NN * HL], g_h016b[NN * HL];
__device__ __half g_h116a[NN * HL], g_h116b[NN * HL];
__device__ __half g_x16[(size_t)TT * NN * 32];          // K padded 16->32
__device__ __half g_wih0hi[G4H * 32],  g_wih0lo[G4H * 32];
__device__ __half g_whh0hi[G4H * HL],  g_whh0lo[G4H * HL];
__device__ __half g_wih1hi[G4H * HL],  g_wih1lo[G4H * HL];
__device__ __half g_whh1hi[G4H * HL],  g_whh1lo[G4H * HL];
__device__ float g_pb0[G4H], g_pb1[G4H];

// ---------------- helpers ---------------------------------------------------
__device__ __forceinline__ void mma_f16(
    float& c0, float& c1, float& c2, float& c3,
    uint32_t a0, uint32_t a1, uint32_t a2, uint32_t a3,
    uint32_t b0, uint32_t b1)
{
    asm volatile(
        "mma.sync.aligned.m16n8k16.row.col.f32.f16.f16.f32 "
        "{%0,%1,%2,%3}, {%4,%5,%6,%7}, {%8,%9}, {%0,%1,%2,%3};"
        : "+f"(c0), "+f"(c1), "+f"(c2), "+f"(c3)
        : "r"(a0), "r"(a1), "r"(a2), "r"(a3), "r"(b0), "r"(b1));
}

// ---------------- weight split + gate permutation ---------------------------
// torch rows [4H x K]: row = q*256+u (q in i,f,g,o). New row (col of gates) =
// (u/32)*128 + q*32 + (u%32) so each 128-col tile has all gates for 32 units.
__global__ void split_perm_f16(const float* __restrict__ w, int K, int Kp,
                               __half* __restrict__ hi,
                               __half* __restrict__ lo, int total)
{
    int idx = blockIdx.x * 256 + threadIdx.x;
    if (idx >= total) return;
    int row = idx / Kp, k = idx % Kp;
    int q = row >> 8, u = row & 255;
    int nr = ((u >> 5) << 7) + (q << 5) + (u & 31);
    float v = (k < K) ? w[(size_t)row * K + k] : 0.f;
    __half h = __float2half(v);
    hi[(size_t)nr * Kp + k] = h;
    lo[(size_t)nr * Kp + k] = __float2half(v - __half2float(h));
}

__global__ void bias_perm(const float* __restrict__ bi, const float* __restrict__ bh,
                          float* __restrict__ pb)
{
    int row = blockIdx.x * 256 + threadIdx.x;
    if (row >= G4H) return;
    int q = row >> 8, u = row & 255;
    int nr = ((u >> 5) << 7) + (q << 5) + (u & 31);
    pb[nr] = bi[row] + bh[row];
}

// ---------------- x convert: [N][T][F] -> fp16 [T][N][32] -------------------
__global__ void conv_x16(const float* __restrict__ x, __half* __restrict__ x16, int n)
{
    size_t idx = (size_t)blockIdx.x * 256 + threadIdx.x;
    if (idx >= (size_t)TT * n * 32) return;
    int k  = idx & 31;
    int rn = (idx >> 5) % n;
    int t  = idx / (32 * (size_t)n);
    float v = (k < FF) ? x[(size_t)rn * TT * FF + t * FF + k] : 0.f;
    x16[idx] = __float2half(v);
}

// ---------------- fused LSTM wavefront step --------------------------------
// One launch computes layer0(t=s) [z=0] and layer1(t=s-1) [z=1] concurrently.
// 2-term fp16: gates = (Whi + Wlo) @ A16, A16 = fp16(activations), fp32 accum.
// Compute mapping identical to verified R13/R15 kernel.
struct PhaseDesc {
    const __half* A;                 // [rows][Kp] fp16 activations
    int Kp;                          // padded K (mult of 32), also row stride
    const __half *Bhi, *Blo;         // [1024][Kp] (permuted rows)
};

#define SROW 136                     // u32 stride for smem rows (bank spread)
#define STAGE_U32 (3 * 16 * SROW)    // 6528 u32 per stage (A, Bh, Bl)
#define STEP_SMEM (128 * 132 * 4)    // 67584 B: sC dominates; stages alias

extern __shared__ uint32_t s_u32[];

__global__ __launch_bounds__(256) void lstm_wave(
    int s,
    const __half* __restrict__ x16,
    __half* __restrict__ h016a, __half* __restrict__ h016b,
    float* __restrict__ c0, const float* __restrict__ pb0,
    const __half* __restrict__ wih0hi, const __half* __restrict__ wih0lo,
    const __half* __restrict__ whh0hi, const __half* __restrict__ whh0lo,
    __half* __restrict__ h116a, __half* __restrict__ h116b,
    float* __restrict__ c1, const float* __restrict__ pb1,
    const __half* __restrict__ wih1hi, const __half* __restrict__ wih1lo,
    const __half* __restrict__ whh1hi, const __half* __restrict__ whh1lo,
    float* __restrict__ h1f, int Nr)
{
    // ---- per-layer setup ----
    PhaseDesc P0, P1;
    __half* h16out;
    float* c;
    float* hf;
    const float* pbias;
    if (blockIdx.z == 0) {
        const int t0 = s;
        if (t0 >= TT) return;
        const int p = t0 & 1;
        P0 = { x16 + (size_t)t0 * Nr * 32, 32, wih0hi, wih0lo };
        P1 = { p ? h016a : h016b, HL, whh0hi, whh0lo };   // read h0(t0-1)
        h16out = p ? h016b : h016a;                        // write h0(t0)
        c = c0; hf = nullptr; pbias = pb0;
    } else {
        const int t1 = s - 1;
        if (t1 < 0) return;
        const int p = t1 & 1;
        P0 = { p ? h016b : h016a, HL, wih1hi, wih1lo };    // read h0(t1)
        P1 = { p ? h116a : h116b, HL, whh1hi, whh1lo };    // read h1(t1-1)
        h16out = p ? h116b : h116a;                        // write h1(t1)
        c = c1; hf = h1f; pbias = pb1;
    }

    float* sC = (float*)s_u32;       // alias, used after compute

    const int tid  = threadIdx.x;
    const int lane = tid & 31;
    const int warp = tid >> 5;
    const int grp  = lane >> 2;      // 0..7
    const int tig  = lane & 3;       // 0..3
    const int wm   = (warp & 1) * 64;
    const int wn   = (warp >> 1) * 32;
    const int rowBase = blockIdx.y * 128;
    const int colBase = blockIdx.x * 128;

    const int n0iters = P0.Kp >> 5;
    const int niters  = n0iters + (P1.Kp >> 5);

    // loader mapping: thread stages row r, 8 kpairs (half)
    const int r    = tid >> 1;       // 0..127
    const int half = tid & 1;
    const int kp0  = half * 8;
    const int gr   = rowBase + r;
    const bool aval = gr < Nr;
    const int br   = colBase + r;

    float acc[4][4][4];
#pragma unroll
    for (int i = 0; i < 4; i++)
#pragma unroll
        for (int j = 0; j < 4; j++)
#pragma unroll
            for (int q = 0; q < 4; q++) acc[i][j][q] = 0.f;

    // prefetch registers
    uint4 Ra0, Ra1, Rbh0, Rbh1, Rbl0, Rbl1;

    auto loadG = [&](int it) {
        const bool ph = it >= n0iters;
        const PhaseDesc& D = ph ? P1 : P0;
        const int k0 = (ph ? it - n0iters : it) << 5;
        if (aval) {
            const uint32_t* p = (const uint32_t*)(D.A + (size_t)gr * D.Kp + k0) + half * 8;
            Ra0 = *(const uint4*)p;
            Ra1 = *(const uint4*)(p + 4);
        } else {
            Ra0 = Ra1 = make_uint4(0u, 0u, 0u, 0u);
        }
        const uint32_t* q = (const uint32_t*)(D.Bhi + (size_t)br * D.Kp + k0) + half * 8;
        Rbh0 = *(const uint4*)q;
        Rbh1 = *(const uint4*)(q + 4);
        q = (const uint32_t*)(D.Blo + (size_t)br * D.Kp + k0) + half * 8;
        Rbl0 = *(const uint4*)q;
        Rbl1 = *(const uint4*)(q + 4);
    };

    auto stoS = [&](int it) {
        uint32_t* st  = s_u32 + (it & 1) * STAGE_U32;
        uint32_t* sA  = st;
        uint32_t* sBh = st + 16 * SROW;
        uint32_t* sBl = st + 32 * SROW;
        uint32_t a[8]  = {Ra0.x, Ra0.y, Ra0.z, Ra0.w, Ra1.x, Ra1.y, Ra1.z, Ra1.w};
        uint32_t bh[8] = {Rbh0.x, Rbh0.y, Rbh0.z, Rbh0.w, Rbh1.x, Rbh1.y, Rbh1.z, Rbh1.w};
        uint32_t bl[8] = {Rbl0.x, Rbl0.y, Rbl0.z, Rbl0.w, Rbl1.x, Rbl1.y, Rbl1.z, Rbl1.w};
#pragma unroll
        for (int i = 0; i < 8; i++) {
            sA[(kp0 + i) * SROW + r]  = a[i];
            sBh[(kp0 + i) * SROW + r] = bh[i];
            sBl[(kp0 + i) * SROW + r] = bl[i];
        }
    };

    loadG(0);
    stoS(0);

#pragma unroll 1
    for (int it = 0; it < niters; it++) {
        if (it + 1 < niters) loadG(it + 1);   // LDGs in flight over compute
        __syncthreads();                       // stage it visible

        const uint32_t* st  = s_u32 + (it & 1) * STAGE_U32;
        const uint32_t* sA  = st;
        const uint32_t* sBh = st + 16 * SROW;
        const uint32_t* sBl = st + 32 * SROW;

        // ---- compute: 2 x k16 halves, 2-term fp16 ----
#pragma unroll
        for (int kh = 0; kh < 2; kh++) {
            const int kb = kh * 8;
            uint32_t bh0[4], bh1[4], bl0[4], bl1[4];
#pragma unroll
            for (int nt = 0; nt < 4; nt++) {
                int n0 = wn + nt * 8 + grp;
                bh0[nt] = sBh[(kb + tig) * SROW + n0];
                bh1[nt] = sBh[(kb + tig + 4) * SROW + n0];
                bl0[nt] = sBl[(kb + tig) * SROW + n0];
                bl1[nt] = sBl[(kb + tig + 4) * SROW + n0];
            }
#pragma unroll
            for (int mt = 0; mt < 4; mt++) {
                int m0 = wm + mt * 16 + grp;
                uint32_t a0 = sA[(kb + tig) * SROW + m0];
                uint32_t a1 = sA[(kb + tig) * SROW + m0 + 8];
                uint32_t a2 = sA[(kb + tig + 4) * SROW + m0];
                uint32_t a3 = sA[(kb + tig + 4) * SROW + m0 + 8];
#pragma unroll
                for (int nt = 0; nt < 4; nt++) {
                    float* cc = acc[mt][nt];
                    mma_f16(cc[0], cc[1], cc[2], cc[3],
                            a0, a1, a2, a3, bh0[nt], bh1[nt]);
                    mma_f16(cc[0], cc[1], cc[2], cc[3],
                            a0, a1, a2, a3, bl0[nt], bl1[nt]);
                }
            }
        }
        __syncthreads();                       // buf (it+1)&1 readers done
        if (it + 1 < niters) stoS(it + 1);
    }

    // ---- stage gates tile to smem (aliases staging buffers) ----
#pragma unroll
    for (int mt = 0; mt < 4; mt++) {
        int rr = wm + mt * 16 + grp;
#pragma unroll
        for (int nt = 0; nt < 4; nt++) {
            int cc = wn + nt * 8 + 2 * tig;
            sC[rr * 132 + cc]           = acc[mt][nt][0];
            sC[rr * 132 + cc + 1]       = acc[mt][nt][1];
            sC[(rr + 8) * 132 + cc]     = acc[mt][nt][2];
            sC[(rr + 8) * 132 + cc + 1] = acc[mt][nt][3];
        }
    }
    __syncthreads();

    // ---- fused LSTM cell: this tile holds all 4 gates for 32 units ----
    const int v  = tid & 31;
    const int rg = tid >> 5;
    const float b_i = pbias[colBase + v];
    const float b_f = pbias[colBase + 32 + v];
    const float b_g = pbias[colBase + 64 + v];
    const float b_o = pbias[colBase + 96 + v];
    const int u = blockIdx.x * 32 + v;
#pragma unroll 4
    for (int i = 0; i < 16; i++) {
        int rr = rg * 16 + i;
        int grr = rowBase + rr;
        if (grr >= Nr) continue;
        float gi = sC[rr * 132 + v]      + b_i;
        float gf = sC[rr * 132 + 32 + v] + b_f;
        float gg = sC[rr * 132 + 64 + v] + b_g;
        float go = sC[rr * 132 + 96 + v] + b_o;
        size_t off = (size_t)grr * HL + u;
        float cp = c[off];
        float si = 1.f / (1.f + __expf(-gi));
        float sf = 1.f / (1.f + __expf(-gf));
        float so = 1.f / (1.f + __expf(-go));
        float cn = sf * cp + si * tanhf(gg);
        float hn = so * tanhf(cn);
        c[off] = cn;
        h16out[off] = __float2half(hn);
        if (hf) hf[off] = hn;
    }
}

// ---------------- GEMM (SIMT fp32) for GAT/MLP -----------------------------
#define BM 128
#define BN 128
#define BK 8

__global__ __launch_bounds__(256) void gemm_dual(
    const float* __restrict__ A1, int lda1, int K1, const float* __restrict__ B1,
    const float* __restrict__ A2, int lda2, int K2, const float* __restrict__ B2,
    const float* __restrict__ bias1, const float* __restrict__ bias2,
    float* __restrict__ C, int Nr, int M, int transB, int act)
{
    __shared__ float As[BK][BM];
    __shared__ float Bs[BK][BN];

    const int tid = threadIdx.x;
    const int tx = tid & 15;
    const int ty = tid >> 4;
    const int rowBase = blockIdx.y * BM;
    const int colBase = blockIdx.x * BN;

    float acc[8][8];
#pragma unroll
    for (int i = 0; i < 8; i++)
#pragma unroll
        for (int j = 0; j < 8; j++) acc[i][j] = 0.f;

    for (int phase = 0; phase < 2; phase++) {
        const float* A = phase ? A2 : A1;
        const float* B = phase ? B2 : B1;
        const int K   = phase ? K2 : K1;
        const int lda = phase ? lda2 : lda1;
        for (int k0 = 0; k0 < K; k0 += BK) {
            {
                int rr = tid >> 1;
                int kq = (tid & 1) * 4;
                int gr = rowBase + rr;
                float4 vv = make_float4(0.f, 0.f, 0.f, 0.f);
                if (gr < Nr)
                    vv = *(const float4*)(A + (size_t)gr * lda + k0 + kq);
                As[kq + 0][rr] = vv.x; As[kq + 1][rr] = vv.y;
                As[kq + 2][rr] = vv.z; As[kq + 3][rr] = vv.w;
            }
            if (transB) {
                int rr = tid >> 1;
                int kq = (tid & 1) * 4;
                float4 vv = *(const float4*)(B + (size_t)(colBase + rr) * K + k0 + kq);
                Bs[kq + 0][rr] = vv.x; Bs[kq + 1][rr] = vv.y;
                Bs[kq + 2][rr] = vv.z; Bs[kq + 3][rr] = vv.w;
            } else {
                int kk = tid >> 5;
                int n4 = (tid & 31) * 4;
                float4 vv = *(const float4*)(B + (size_t)(k0 + kk) * M + colBase + n4);
                Bs[kk][n4 + 0] = vv.x; Bs[kk][n4 + 1] = vv.y;
                Bs[kk][n4 + 2] = vv.z; Bs[kk][n4 + 3] = vv.w;
            }
            __syncthreads();
#pragma unroll
            for (int k = 0; k < BK; k++) {
                float4 a0 = *(const float4*)&As[k][ty * 8];
                float4 a1 = *(const float4*)&As[k][ty * 8 + 4];
                float4 b0 = *(const float4*)&Bs[k][tx * 8];
                float4 b1 = *(const float4*)&Bs[k][tx * 8 + 4];
                float ra[8] = {a0.x, a0.y, a0.z, a0.w, a1.x, a1.y, a1.z, a1.w};
                float rb[8] = {b0.x, b0.y, b0.z, b0.w, b1.x, b1.y, b1.z, b1.w};
#pragma unroll
                for (int i = 0; i < 8; i++)
#pragma unroll
                    for (int j = 0; j < 8; j++)
                        acc[i][j] = fmaf(ra[i], rb[j], acc[i][j]);
            }
            __syncthreads();
        }
    }

#pragma unroll
    for (int i = 0; i < 8; i++) {
        int gr = rowBase + ty * 8 + i;
        if (gr >= Nr) continue;
#pragma unroll
        for (int j = 0; j < 8; j++) {
            int gc = colBase + tx * 8 + j;
            float vv = acc[i][j];
            if (bias1) vv += bias1[gc];
            if (bias2) vv += bias2[gc];
            if (act == 1) vv = fmaxf(vv, 0.f);
            C[(size_t)gr * M + gc] = vv;
        }
    }
}

// ---------------- edge_attr mean (deterministic 2-stage) -------------------
__global__ void reduce_mean1(const float* __restrict__ ea, int E)
{
    __shared__ float s[256];
    int tid = threadIdx.x;
    float acc = 0.f;
    for (int i = blockIdx.x * 256 + tid; i < E; i += 256 * 256) acc += ea[i];
    s[tid] = acc;
    __syncthreads();
    for (int off = 128; off > 0; off >>= 1) {
        if (tid < off) s[tid] += s[tid + off];
        __syncthreads();
    }
    if (tid == 0) g_partial[blockIdx.x] = s[0];
}

__global__ void reduce_mean2(int E)
{
    __shared__ float s[256];
    int tid = threadIdx.x;
    s[tid] = g_partial[tid];
    __syncthreads();
    for (int off = 128; off > 0; off >>= 1) {
        if (tid < off) s[tid] += s[tid + off];
        __syncthreads();
    }
    if (tid == 0) g_mean_buf[0] = s[0] / (float)E;
}

// ---------------- GAT edge pass 1: logits -> exp, accumulate denominator ---
__global__ void gat_edge_logits(
    const int* __restrict__ src, const int* __restrict__ dst,
    const float* __restrict__ ea,
    const float* __restrict__ we, const float* __restrict__ att,
    const float* __restrict__ xl, const float* __restrict__ xr,
    float* __restrict__ expl, float* __restrict__ den,
    int E, int Etot)
{
    int idx = blockIdx.x * blockDim.x + threadIdx.x;
    if (idx >= Etot * GH) return;
    int e = idx >> 3;
    int h = idx & 7;
    int s, d; float a;
    if (e < E) { s = src[e]; d = dst[e]; a = ea[e]; }
    else       { s = d = e - E;          a = g_mean_buf[0]; }

    const float4* pl = (const float4*)(xl + (size_t)s * GD + h * GC);
    const float4* pr = (const float4*)(xr + (size_t)d * GD + h * GC);
    const float4* pw = (const float4*)(we + h * GC);
    const float4* pa = (const float4*)(att + h * GC);

    float acc = 0.f;
#pragma unroll
    for (int c4 = 0; c4 < GC / 4; c4++) {
        float4 vl = pl[c4], vr = pr[c4], vw = pw[c4], va = pa[c4];
        float m;
        m = vl.x + vr.x + a * vw.x; m = m > 0.f ? m : 0.2f * m; acc += m * va.x;
        m = vl.y + vr.y + a * vw.y; m = m > 0.f ? m : 0.2f * m; acc += m * va.y;
        m = vl.z + vr.z + a * vw.z; m = m > 0.f ? m : 0.2f * m; acc += m * va.z;
        m = vl.w + vr.w + a * vw.w; m = m > 0.f ? m : 0.2f * m; acc += m * va.w;
    }
    float ex = __expf(acc);
    expl[idx] = ex;
    atomicAdd(&den[d * GH + h], ex);
}

// ---------------- GAT edge pass 2: weighted aggregation --------------------
__global__ void gat_edge_aggr(
    const int* __restrict__ src, const int* __restrict__ dst,
    const float* __restrict__ xl,
    const float* __restrict__ expl, const float* __restrict__ den,
    float* __restrict__ gout,
    int E, int Etot)
{
    int idx = blockIdx.x * blockDim.x + threadIdx.x;
    if (idx >= Etot * GH) return;
    int e = idx >> 3;
    int h = idx & 7;
    int s, d;
    if (e < E) { s = src[e]; d = dst[e]; }
    else       { s = d = e - E; }

    float alpha = expl[idx] / den[d * GH + h];
    const float4* pl = (const float4*)(xl + (size_t)s * GD + h * GC);
    float* po = gout + (size_t)d * GD + h * GC;
#pragma unroll
    for (int c4 = 0; c4 < GC / 4; c4++) {
        float4 vv = pl[c4];
        atomicAdd(&po[c4 * 4 + 0], vv.x * alpha);
        atomicAdd(&po[c4 * 4 + 1], vv.y * alpha);
        atomicAdd(&po[c4 * 4 + 2], vv.z * alpha);
        atomicAdd(&po[c4 * 4 + 3], vv.w * alpha);
    }
}

// ---------------- GAT finalize: +bias, ELU ---------------------------------
__global__ void gat_finalize(const float* __restrict__ gout,
                             const float* __restrict__ bias,
                             float* __restrict__ out, int total)
{
    int idx = blockIdx.x * blockDim.x + threadIdx.x;
    if (idx >= total) return;
    float vv = gout[idx] + bias[idx & (GD - 1)];
    out[idx] = vv > 0.f ? vv : expm1f(vv);
}

// ---------------- fc2 GEMV -------------------------------------------------
__global__ void gemv_fc2(const float* __restrict__ hbuf,
                         const float* __restrict__ w, const float* __restrict__ b,
                         float* __restrict__ out, int n)
{
    int gw = (blockIdx.x * blockDim.x + threadIdx.x) >> 5;
    int lane = threadIdx.x & 31;
    if (gw >= n) return;
    const float* row = hbuf + (size_t)gw * FH;
    float acc = 0.f;
#pragma unroll
    for (int k = lane; k < FH; k += 32) acc += row[k] * w[k];
#pragma unroll
    for (int off = 16; off > 0; off >>= 1) acc += __shfl_xor_sync(0xffffffffu, acc, off);
    if (lane == 0) out[gw] = acc + b[0];
}

// ---------------- host orchestration ---------------------------------------
static inline void run_gemm(const float* A1, int lda1, int K1, const float* B1,
                            const float* A2, int lda2, int K2, const float* B2,
                            const float* bias1, const float* bias2,
                            float* C, int Nr, int M, int transB, int act)
{
    dim3 grid((M + BN - 1) / BN, (Nr + BM - 1) / BM);
    gemm_dual<<<grid, 256>>>(A1, lda1, K1, B1, A2, lda2, K2, B2,
                             bias1, bias2, C, Nr, M, transB, act);
}

extern "C" void kernel_launch(void* const* d_in, const int* in_sizes, int n_in,
                              void* d_out, int out_size)
{
    const float* x_seq  = (const float*)d_in[0];
    const int*   eidx   = (const int*)  d_in[1];
    const float* eattr  = (const float*)d_in[2];
    const float* w_ih0  = (const float*)d_in[3];
    const float* w_hh0  = (const float*)d_in[4];
    const float* b_ih0  = (const float*)d_in[5];
    const float* b_hh0  = (const float*)d_in[6];
    const float* w_ih1  = (const float*)d_in[7];
    const float* w_hh1  = (const float*)d_in[8];
    const float* b_ih1  = (const float*)d_in[9];
    const float* b_hh1  = (const float*)d_in[10];
    const float* g0_wl  = (const float*)d_in[11];
    const float* g0_bl  = (const float*)d_in[12];
    const float* g0_wr  = (const float*)d_in[13];
    const float* g0_br  = (const float*)d_in[14];
    const float* g0_we  = (const float*)d_in[15];
    const float* g0_att = (const float*)d_in[16];
    const float* g0_bias= (const float*)d_in[17];
    const float* g1_wl  = (const float*)d_in[18];
    const float* g1_bl  = (const float*)d_in[19];
    const float* g1_wr  = (const float*)d_in[20];
    const float* g1_br  = (const float*)d_in[21];
    const float* g1_we  = (const float*)d_in[22];
    const float* g1_att = (const float*)d_in[23];
    const float* g1_bias= (const float*)d_in[24];
    const float* fc1_w  = (const float*)d_in[25];
    const float* fc1_b  = (const float*)d_in[26];
    const float* fc2_w  = (const float*)d_in[27];
    const float* fc2_b  = (const float*)d_in[28];

    const int n = in_sizes[0] / (TT * FF);
    const int E = in_sizes[2];
    const int Etot = E + n;
    const int* src = eidx;
    const int* dst = eidx + E;

    float *c0, *h1, *c1, *xl, *xr, *gout, *gin, *den, *fc1buf, *pb0, *pb1;
    __half *h016a, *h016b, *h116a, *h116b, *x16;
    __half *wih0hi, *wih0lo, *whh0hi, *whh0lo, *wih1hi, *wih1lo, *whh1hi, *whh1lo;
    cudaGetSymbolAddress((void**)&c0, g_c0);
    cudaGetSymbolAddress((void**)&h1, g_h1);
    cudaGetSymbolAddress((void**)&c1, g_c1);
    cudaGetSymbolAddress((void**)&xl, g_xl);
    cudaGetSymbolAddress((void**)&xr, g_xr);
    cudaGetSymbolAddress((void**)&gout, g_gout);
    cudaGetSymbolAddress((void**)&gin, g_gin);
    cudaGetSymbolAddress((void**)&den, g_den);
    cudaGetSymbolAddress((void**)&fc1buf, g_fc1);
    cudaGetSymbolAddress((void**)&pb0, g_pb0);
    cudaGetSymbolAddress((void**)&pb1, g_pb1);
    cudaGetSymbolAddress((void**)&h016a, g_h016a);
    cudaGetSymbolAddress((void**)&h016b, g_h016b);
    cudaGetSymbolAddress((void**)&h116a, g_h116a);
    cudaGetSymbolAddress((void**)&h116b, g_h116b);
    cudaGetSymbolAddress((void**)&x16, g_x16);
    cudaGetSymbolAddress((void**)&wih0hi, g_wih0hi);
    cudaGetSymbolAddress((void**)&wih0lo, g_wih0lo);
    cudaGetSymbolAddress((void**)&whh0hi, g_whh0hi);
    cudaGetSymbolAddress((void**)&whh0lo, g_whh0lo);
    cudaGetSymbolAddress((void**)&wih1hi, g_wih1hi);
    cudaGetSymbolAddress((void**)&wih1lo, g_wih1lo);
    cudaGetSymbolAddress((void**)&whh1hi, g_whh1hi);
    cudaGetSymbolAddress((void**)&whh1lo, g_whh1lo);

    static int smem_set = 0;
    if (!smem_set) {
        cudaFuncSetAttribute(lstm_wave, cudaFuncAttributeMaxDynamicSharedMemorySize,
                             STEP_SMEM);
        smem_set = 1;
    }

    // init states (fp16 zero = 0x0000)
    cudaMemsetAsync(c0, 0, (size_t)n * HL * sizeof(float));
    cudaMemsetAsync(c1, 0, (size_t)n * HL * sizeof(float));
    cudaMemsetAsync(h016a, 0, (size_t)n * HL * sizeof(__half));
    cudaMemsetAsync(h016b, 0, (size_t)n * HL * sizeof(__half));
    cudaMemsetAsync(h116a, 0, (size_t)n * HL * sizeof(__half));
    cudaMemsetAsync(h116b, 0, (size_t)n * HL * sizeof(__half));

    // edge_attr mean (for self-loop fill)
    reduce_mean1<<<256, 256>>>(eattr, E);
    reduce_mean2<<<1, 256>>>(E);

    // split + permute LSTM weights to fp16 hi/lo; convert x to fp16
    split_perm_f16<<<(G4H * 32 + 255) / 256, 256>>>(w_ih0, FF, 32, wih0hi, wih0lo, G4H * 32);
    split_perm_f16<<<(G4H * HL + 255) / 256, 256>>>(w_hh0, HL, HL, whh0hi, whh0lo, G4H * HL);
    split_perm_f16<<<(G4H * HL + 255) / 256, 256>>>(w_ih1, HL, HL, wih1hi, wih1lo, G4H * HL);
    split_perm_f16<<<(G4H * HL + 255) / 256, 256>>>(w_hh1, HL, HL, whh1hi, whh1lo, G4H * HL);
    bias_perm<<<4, 256>>>(b_ih0, b_hh0, pb0);
    bias_perm<<<4, 256>>>(b_ih1, b_hh1, pb1);
    {
        size_t tot = (size_t)TT * n * 32;
        conv_x16<<<(int)((tot + 255) / 256), 256>>>(x_seq, x16, n);
    }

    // ------------- LSTM: wavefront (layer0 t=s, layer1 t=s-1 per launch) --
    dim3 wgrid(8, (n + 127) / 128, 2);
    for (int s = 0; s <= TT; s++) {
        lstm_wave<<<wgrid, 256, STEP_SMEM>>>(
            s, x16,
            h016a, h016b, c0, pb0, wih0hi, wih0lo, whh0hi, whh0lo,
            h116a, h116b, c1, pb1, wih1hi, wih1lo, whh1hi, whh1lo,
            h1, n);
    }
    // node features = h1 (layer-1 hidden at last step)

    const int edgeThreads = Etot * GH;
    const int edgeBlocks  = (edgeThreads + 255) / 256;
    const int ndTot = n * GD;

    // ------------- GAT layer 0 (input: h1, K=256) -------------
    run_gemm(h1, HL, HL, g0_wl, nullptr, 0, 0, nullptr, g0_bl, nullptr,
             xl, n, GD, /*transB=*/0, 0);
    run_gemm(h1, HL, HL, g0_wr, nullptr, 0, 0, nullptr, g0_br, nullptr,
             xr, n, GD, 0, 0);
    cudaMemsetAsync(den, 0, (size_t)n * GH * sizeof(float));
    cudaMemsetAsync(gout, 0, (size_t)ndTot * sizeof(float));
    gat_edge_logits<<<edgeBlocks, 256>>>(src, dst, eattr, g0_we, g0_att,
                                         xl, xr, g_expl, den, E, Etot);
    gat_edge_aggr<<<edgeBlocks, 256>>>(src, dst, xl, g_expl, den, gout, E, Etot);
    gat_finalize<<<(ndTot + 255) / 256, 256>>>(gout, g0_bias, gin, ndTot);

    // ------------- GAT layer 1 (input: gin, K=512) -------------
    run_gemm(gin, GD, GD, g1_wl, nullptr, 0, 0, nullptr, g1_bl, nullptr,
             xl, n, GD, 0, 0);
    run_gemm(gin, GD, GD, g1_wr, nullptr, 0, 0, nullptr, g1_br, nullptr,
             xr, n, GD, 0, 0);
    cudaMemsetAsync(den, 0, (size_t)n * GH * sizeof(float));
    cudaMemsetAsync(gout, 0, (size_t)ndTot * sizeof(float));
    gat_edge_logits<<<edgeBlocks, 256>>>(src, dst, eattr, g1_we, g1_att,
                                         xl, xr, g_expl, den, E, Etot);
    gat_edge_aggr<<<edgeBlocks, 256>>>(src, dst, xl, g_expl, den, gout, E, Etot);
    gat_finalize<<<(ndTot + 255) / 256, 256>>>(gout, g1_bias, gin, ndTot);

    // ------------- fusion MLP -------------
    run_gemm(h1, HL, HL, fc1_w,
             gin, GD, GD, fc1_w + (size_t)HL * FH,
             fc1_b, nullptr, fc1buf, n, FH, /*transB=*/0, /*act=*/1);
    gemv_fc2<<<(n * 32 + 255) / 256, 256>>>(fc1buf, fc2_w, fc2_b,
                                            (float*)d_out, n);
}